// round 3
// baseline (speedup 1.0000x reference)
#include <cuda_runtime.h>
#include <math.h>

#define NN 32768
#define NE 4096
#define NI 131072
#define DM 256
#define EPSV 1e-5f
#define NEGS 0.2f

// ------------------------- device scratch -------------------------
__device__ float g_h1[NN * DM];        // post bn1 node features
__device__ float g_xh[NN * 2 * DM];    // h1 @ attW^T  (reused as h3 output later)
__device__ float g_eattr[NE * DM];
__device__ float g_edge_out[NE * 2 * DM];
__device__ float g_hb[NN * DM];        // bn2(h1 + x2)
__device__ float g_sn[NN * 2];
__device__ float g_se[NE * 2];
__device__ float g_alpha[NI * 2];
__device__ float g_wn[2 * DM];
__device__ float g_we[2 * DM];
__device__ float g_dinv[NN];
__device__ int g_cnt_n[NN], g_off_n[NN + 1], g_cur_n[NN];
__device__ int g_cnt_e[NE], g_off_e[NE + 1], g_cur_e[NE];
__device__ int g_perm_n[NI], g_perm_e[NI];

__device__ __forceinline__ float leaky(float v) { return v >= 0.f ? v : NEGS * v; }

// ------------------------- CSR build -------------------------
__global__ void k_zero_int(int* a, int n) {
    int i = blockIdx.x * blockDim.x + threadIdx.x;
    if (i < n) a[i] = 0;
}

__global__ void k_hist(const int* __restrict__ idx_n, const int* __restrict__ idx_e) {
    int i = blockIdx.x * blockDim.x + threadIdx.x;
    if (i < NI) {
        atomicAdd(&g_cnt_n[idx_n[i]], 1);
        atomicAdd(&g_cnt_e[idx_e[i]], 1);
    }
}

// single-block exclusive scan (n <= 1024 * L)
__global__ void k_scan(const int* __restrict__ cnt, int* __restrict__ off,
                       int* __restrict__ cur, int n) {
    __shared__ int part[1024];
    int t = threadIdx.x;
    int L = (n + 1023) / 1024;
    int s = 0;
    for (int j = 0; j < L; j++) {
        int idx = t * L + j;
        if (idx < n) s += cnt[idx];
    }
    part[t] = s;
    __syncthreads();
    // Hillis-Steele inclusive scan
    for (int d = 1; d < 1024; d <<= 1) {
        int v = (t >= d) ? part[t - d] : 0;
        __syncthreads();
        part[t] += v;
        __syncthreads();
    }
    int run = (t == 0) ? 0 : part[t - 1];
    for (int j = 0; j < L; j++) {
        int idx = t * L + j;
        if (idx < n) {
            off[idx] = run;
            cur[idx] = run;
            run += cnt[idx];
        }
    }
    if (t == 1023) off[n] = run;
}

__global__ void k_scatter(const int* __restrict__ idx_n, const int* __restrict__ idx_e) {
    int i = blockIdx.x * blockDim.x + threadIdx.x;
    if (i < NI) {
        int p = atomicAdd(&g_cur_n[idx_n[i]], 1);
        g_perm_n[p] = i;
        int q = atomicAdd(&g_cur_e[idx_e[i]], 1);
        g_perm_e[q] = i;
    }
}

// ------------------------- contracted attention vectors -------------------------
// w_n[h][k] = sum_d attW[h*256+d][k] * att[h][d]
// w_e[h][k] = sum_d attW[h*256+d][k] * att[h][256+d]
__global__ void k_prepw(const float* __restrict__ attW, const float* __restrict__ att) {
    int t = threadIdx.x;       // 0..511
    int h = t / DM, k = t % DM;
    float accn = 0.f, acce = 0.f;
    for (int d = 0; d < DM; d++) {
        float w = attW[(h * DM + d) * DM + k];
        accn += w * att[h * 2 * DM + d];
        acce += w * att[h * 2 * DM + DM + d];
    }
    g_wn[t] = accn;
    g_we[t] = acce;
}

// ------------------------- GEMM: C[M,Nw] = A[M,256] @ W[Nw,256]^T -------------------------
// MODE 0: bn1(leaky(acc + bias))   MODE 1: raw   MODE 2: leaky(acc + bias)
template <int MODE>
__global__ void __launch_bounds__(256) k_gemm(
    const float* __restrict__ A, const float* __restrict__ W,
    float* __restrict__ C, int Nw,
    const float* __restrict__ bias,
    const float* __restrict__ bg, const float* __restrict__ bb,
    const float* __restrict__ bm, const float* __restrict__ bv) {
    __shared__ float As[32][68];
    __shared__ float Ws[32][68];
    int tid = threadIdx.x;
    int m0 = blockIdx.y * 64, n0 = blockIdx.x * 64;
    int lr = tid / 8;             // 0..31
    int lc = (tid % 8) * 4;       // 0..28
    int tm = (tid % 16) * 4;
    int tn = (tid / 16) * 4;

    float acc[4][4];
#pragma unroll
    for (int i = 0; i < 4; i++)
#pragma unroll
        for (int j = 0; j < 4; j++) acc[i][j] = 0.f;

    for (int k0 = 0; k0 < 256; k0 += 32) {
#pragma unroll
        for (int r = 0; r < 2; r++) {
            float4 av = *(const float4*)&A[(size_t)(m0 + lr + r * 32) * 256 + k0 + lc];
            As[lc + 0][lr + r * 32] = av.x;
            As[lc + 1][lr + r * 32] = av.y;
            As[lc + 2][lr + r * 32] = av.z;
            As[lc + 3][lr + r * 32] = av.w;
            float4 wv = *(const float4*)&W[(size_t)(n0 + lr + r * 32) * 256 + k0 + lc];
            Ws[lc + 0][lr + r * 32] = wv.x;
            Ws[lc + 1][lr + r * 32] = wv.y;
            Ws[lc + 2][lr + r * 32] = wv.z;
            Ws[lc + 3][lr + r * 32] = wv.w;
        }
        __syncthreads();
#pragma unroll
        for (int k = 0; k < 32; k++) {
            float4 a = *(const float4*)&As[k][tm];
            float4 w = *(const float4*)&Ws[k][tn];
            float af[4] = {a.x, a.y, a.z, a.w};
            float wf[4] = {w.x, w.y, w.z, w.w};
#pragma unroll
            for (int i = 0; i < 4; i++)
#pragma unroll
                for (int j = 0; j < 4; j++) acc[i][j] += af[i] * wf[j];
        }
        __syncthreads();
    }

#pragma unroll
    for (int i = 0; i < 4; i++) {
        int m = m0 + tm + i;
#pragma unroll
        for (int j = 0; j < 4; j++) {
            int n = n0 + tn + j;
            float v = acc[i][j];
            if (MODE == 0) {
                v = leaky(v + bias[n]);
                v = bg[n] * (v - bm[n]) * rsqrtf(bv[n] + EPSV) + bb[n];
            } else if (MODE == 2) {
                v = leaky(v + bias[n]);
            }
            C[(size_t)m * Nw + n] = v;
        }
    }
}

// ------------------------- edge feature aggregation -------------------------
__global__ void k_eattr(const int* __restrict__ idx_n) {
    int e = blockIdx.x;
    int d = threadIdx.x;   // 256
    int s = g_off_e[e], t = g_off_e[e + 1];
    float acc = 0.f;
    for (int j = s; j < t; j++) {
        int n = idx_n[g_perm_e[j]];
        acc += g_h1[(size_t)n * DM + d];
    }
    g_eattr[(size_t)e * DM + d] = acc;
}

// ------------------------- per-row 2-head dot: out[r][h] = X[r,:]·Wv[h,:] -------------------------
__global__ void k_dot(const float* __restrict__ X, const float* __restrict__ Wv,
                      float* __restrict__ out, int rows) {
    int gw = (blockIdx.x * blockDim.x + threadIdx.x) / 32;
    int lane = threadIdx.x & 31;
    if (gw >= rows * 2) return;
    int r = gw / 2, h = gw % 2;
    float acc = 0.f;
    for (int k = lane; k < DM; k += 32) acc += X[(size_t)r * DM + k] * Wv[h * DM + k];
#pragma unroll
    for (int o = 16; o > 0; o >>= 1) acc += __shfl_down_sync(0xffffffffu, acc, o);
    if (lane == 0) out[r * 2 + h] = acc;
}

// ------------------------- per-node segment softmax -------------------------
__global__ void k_softmax(const int* __restrict__ idx_e) {
    int n = blockIdx.x * blockDim.x + threadIdx.x;
    if (n >= NN) return;
    int s = g_off_n[n], t = g_off_n[n + 1];
    int deg = t - s;
    g_dinv[n] = deg > 0 ? 1.0f / (float)deg : 0.0f;
    if (deg == 0) return;
    float sn0 = g_sn[n * 2], sn1 = g_sn[n * 2 + 1];
    float m0 = -3.402823e38f, m1 = -3.402823e38f;
    for (int j = s; j < t; j++) {
        int i = g_perm_n[j];
        int e = idx_e[i];
        float a0 = leaky(sn0 + g_se[e * 2]);
        float a1 = leaky(sn1 + g_se[e * 2 + 1]);
        m0 = fmaxf(m0, a0);
        m1 = fmaxf(m1, a1);
    }
    float d0 = 0.f, d1 = 0.f;
    for (int j = s; j < t; j++) {
        int i = g_perm_n[j];
        int e = idx_e[i];
        float e0 = expf(leaky(sn0 + g_se[e * 2]) - m0);
        float e1 = expf(leaky(sn1 + g_se[e * 2 + 1]) - m1);
        d0 += e0;
        d1 += e1;
        g_alpha[i * 2] = e0;
        g_alpha[i * 2 + 1] = e1;
    }
    float r0 = 1.0f / (d0 + 1e-16f);
    float r1 = 1.0f / (d1 + 1e-16f);
    for (int j = s; j < t; j++) {
        int i = g_perm_n[j];
        g_alpha[i * 2] *= r0;
        g_alpha[i * 2 + 1] *= r1;
    }
}

// ------------------------- edge_out[e,h,d] = Binv * sum alpha * xh[n,h,d] -------------------------
__global__ void __launch_bounds__(512) k_edgeout(const int* __restrict__ idx_n) {
    int e = blockIdx.x;
    int t = threadIdx.x;   // 512 : h*256 + d
    int h = t >> 8;
    int s = g_off_e[e], en = g_off_e[e + 1];
    float binv = (en > s) ? 1.0f / (float)(en - s) : 0.0f;
    float acc = 0.f;
    for (int j = s; j < en; j++) {
        int i = g_perm_e[j];
        int n = idx_n[i];
        acc += g_alpha[i * 2 + h] * g_xh[(size_t)n * 512 + t];
    }
    g_edge_out[(size_t)e * 512 + t] = binv * acc;
}

// ------------------------- node_out + mean heads + cb + bn2 -------------------------
__global__ void __launch_bounds__(256) k_nodeout(
    const int* __restrict__ idx_e, const float* __restrict__ cb,
    const float* __restrict__ g2, const float* __restrict__ b2,
    const float* __restrict__ m2, const float* __restrict__ v2) {
    int n = blockIdx.x;
    int d = threadIdx.x;   // 256
    int s = g_off_n[n], t = g_off_n[n + 1];
    float acc0 = 0.f, acc1 = 0.f;
    for (int j = s; j < t; j++) {
        int i = g_perm_n[j];
        int e = idx_e[i];
        acc0 += g_alpha[i * 2] * g_edge_out[(size_t)e * 512 + d];
        acc1 += g_alpha[i * 2 + 1] * g_edge_out[(size_t)e * 512 + 256 + d];
    }
    float x2 = g_dinv[n] * 0.5f * (acc0 + acc1) + cb[d];
    float v = g_h1[(size_t)n * DM + d] + x2;
    v = g2[d] * (v - m2[d]) * rsqrtf(v2[d] + EPSV) + b2[d];
    g_hb[(size_t)n * DM + d] = v;
}

// ------------------------- residual + LayerNorm over 64-chunks -------------------------
__global__ void k_ln(const float* __restrict__ x, const float* __restrict__ h3,
                     const float* __restrict__ lg, const float* __restrict__ lb,
                     float* __restrict__ out) {
    int g = (blockIdx.x * blockDim.x + threadIdx.x) >> 5;   // one warp per 64-group
    int lane = threadIdx.x & 31;
    if (g >= NI) return;   // NI == 131072 groups
    size_t base = (size_t)g * 64;
    float y0 = x[base + lane] + h3[base + lane];
    float y1 = x[base + 32 + lane] + h3[base + 32 + lane];
    float s = y0 + y1;
#pragma unroll
    for (int o = 16; o > 0; o >>= 1) s += __shfl_xor_sync(0xffffffffu, s, o);
    float mu = s * (1.0f / 64.0f);
    float d0 = y0 - mu, d1 = y1 - mu;
    float vv = d0 * d0 + d1 * d1;
#pragma unroll
    for (int o = 16; o > 0; o >>= 1) vv += __shfl_xor_sync(0xffffffffu, vv, o);
    float rs = rsqrtf(vv * (1.0f / 64.0f) + EPSV);
    out[base + lane] = lg[lane] * d0 * rs + lb[lane];
    out[base + 32 + lane] = lg[lane + 32] * d1 * rs + lb[lane + 32];
}

// ------------------------- launch -------------------------
extern "C" void kernel_launch(void* const* d_in, const int* in_sizes, int n_in,
                              void* d_out, int out_size) {
    const float* x    = (const float*)d_in[0];
    const int*   he   = (const int*)d_in[1];
    const int*   idx_n = he;
    const int*   idx_e = he + NI;
    const float* W1   = (const float*)d_in[2];
    const float* b1   = (const float*)d_in[3];
    const float* bn1g = (const float*)d_in[4];
    const float* bn1b = (const float*)d_in[5];
    const float* bn1m = (const float*)d_in[6];
    const float* bn1v = (const float*)d_in[7];
    const float* attW = (const float*)d_in[8];
    const float* att  = (const float*)d_in[9];
    const float* cb   = (const float*)d_in[10];
    const float* bn2g = (const float*)d_in[11];
    const float* bn2b = (const float*)d_in[12];
    const float* bn2m = (const float*)d_in[13];
    const float* bn2v = (const float*)d_in[14];
    const float* W2   = (const float*)d_in[15];
    const float* b2   = (const float*)d_in[16];
    const float* lng  = (const float*)d_in[17];
    const float* lnb  = (const float*)d_in[18];
    float* out = (float*)d_out;

    float *p_h1, *p_xh, *p_eattr, *p_hb, *p_sn, *p_se, *p_wn, *p_we;
    int *p_cnt_n, *p_cnt_e, *p_off_n, *p_off_e, *p_cur_n, *p_cur_e;
    cudaGetSymbolAddress((void**)&p_h1, g_h1);
    cudaGetSymbolAddress((void**)&p_xh, g_xh);
    cudaGetSymbolAddress((void**)&p_eattr, g_eattr);
    cudaGetSymbolAddress((void**)&p_hb, g_hb);
    cudaGetSymbolAddress((void**)&p_sn, g_sn);
    cudaGetSymbolAddress((void**)&p_se, g_se);
    cudaGetSymbolAddress((void**)&p_wn, g_wn);
    cudaGetSymbolAddress((void**)&p_we, g_we);
    cudaGetSymbolAddress((void**)&p_cnt_n, g_cnt_n);
    cudaGetSymbolAddress((void**)&p_cnt_e, g_cnt_e);
    cudaGetSymbolAddress((void**)&p_off_n, g_off_n);
    cudaGetSymbolAddress((void**)&p_off_e, g_off_e);
    cudaGetSymbolAddress((void**)&p_cur_n, g_cur_n);
    cudaGetSymbolAddress((void**)&p_cur_e, g_cur_e);

    // ---- CSR build ----
    k_zero_int<<<(NN + 255) / 256, 256>>>(p_cnt_n, NN);
    k_zero_int<<<(NE + 255) / 256, 256>>>(p_cnt_e, NE);
    k_hist<<<(NI + 255) / 256, 256>>>(idx_n, idx_e);
    k_scan<<<1, 1024>>>(p_cnt_n, p_off_n, p_cur_n, NN);
    k_scan<<<1, 1024>>>(p_cnt_e, p_off_e, p_cur_e, NE);
    k_scatter<<<(NI + 255) / 256, 256>>>(idx_n, idx_e);

    // ---- contracted attention weight vectors ----
    k_prepw<<<1, 512>>>(attW, att);

    // ---- GEMM 1: h1 = bn1(leaky(x @ W1^T + b1)) ----
    {
        dim3 grid(DM / 64, NN / 64);
        k_gemm<0><<<grid, 256>>>(x, W1, p_h1, DM, b1, bn1g, bn1b, bn1m, bn1v);
    }

    // ---- edge features + scores ----
    k_eattr<<<NE, 256>>>(idx_n);
    k_dot<<<(NN * 2 * 32 + 255) / 256, 256>>>(p_h1, p_wn, p_sn, NN);
    k_dot<<<(NE * 2 * 32 + 255) / 256, 256>>>(p_eattr, p_we, p_se, NE);

    // ---- GEMM 2: xh = h1 @ attW^T  [NN, 512] ----
    {
        dim3 grid(512 / 64, NN / 64);
        k_gemm<1><<<grid, 256>>>(p_h1, attW, p_xh, 512, nullptr, nullptr, nullptr, nullptr, nullptr);
    }

    // ---- segment softmax ----
    k_softmax<<<(NN + 255) / 256, 256>>>(idx_e);

    // ---- message passing ----
    k_edgeout<<<NE, 512>>>(idx_n);
    k_nodeout<<<NN, 256>>>(idx_e, cb, bn2g, bn2b, bn2m, bn2v);

    // ---- GEMM 3: h3 = leaky(hb @ W2^T + b2)  (reuse g_xh as h3) ----
    {
        dim3 grid(DM / 64, NN / 64);
        k_gemm<2><<<grid, 256>>>(p_hb, W2, p_xh, DM, b2, nullptr, nullptr, nullptr, nullptr);
    }

    // ---- residual + LayerNorm ----
    k_ln<<<(NI * 32 + 255) / 256, 256>>>(x, p_xh, lng, lnb, out);
}

// round 4
// speedup vs baseline: 2.2299x; 2.2299x over previous
#include <cuda_runtime.h>
#include <math.h>

#define NN 32768
#define NE 4096
#define NI 131072
#define DM 256
#define EPSV 1e-5f
#define NEGS 0.2f

// ------------------------- device scratch -------------------------
__device__ float g_h1[NN * DM];        // post bn1 node features
__device__ float g_xh[NN * 2 * DM];    // h1 @ attW^T  (reused as h3 output later)
__device__ float g_eattr[NE * DM];
__device__ float g_edge_out[NE * 2 * DM];
__device__ float g_hb[NN * DM];        // bn2(h1 + x2)
__device__ float g_sn[NN * 2];
__device__ float g_se[NE * 2];
__device__ float g_alpha[NI * 2];
__device__ float g_wn[2 * DM];
__device__ float g_we[2 * DM];
__device__ float g_dinv[NN];
__device__ int g_cnt_n[NN], g_off_n[NN + 1], g_cur_n[NN];
__device__ int g_cnt_e[NE], g_off_e[NE + 1], g_cur_e[NE];
__device__ int g_perm_n[NI], g_perm_e[NI];
__device__ int g_bsum_n[32], g_bsum_e[4];

__device__ __forceinline__ float leaky(float v) { return v >= 0.f ? v : NEGS * v; }

__device__ __forceinline__ unsigned f2tf32(float f) {
    unsigned r;
    asm("cvt.rna.tf32.f32 %0, %1;" : "=r"(r) : "f"(f));
    return r;
}

// ------------------------- CSR build -------------------------
__global__ void k_zero_int(int* a, int n) {
    int i = blockIdx.x * blockDim.x + threadIdx.x;
    if (i < n) a[i] = 0;
}

__global__ void k_hist(const int* __restrict__ idx_n, const int* __restrict__ idx_e) {
    int i = blockIdx.x * blockDim.x + threadIdx.x;
    if (i < NI) {
        atomicAdd(&g_cnt_n[idx_n[i]], 1);
        atomicAdd(&g_cnt_e[idx_e[i]], 1);
    }
}

// Hierarchical scan: phase 1 — per-1024-tile exclusive scan, record tile sums.
__global__ void k_scan_local(const int* __restrict__ cnt, int* __restrict__ off,
                             int* __restrict__ bsum, int n) {
    __shared__ int ws[32];
    int t = threadIdx.x;
    int i = blockIdx.x * 1024 + t;
    int v = (i < n) ? cnt[i] : 0;
    int lane = t & 31, w = t >> 5;
    int s = v;
#pragma unroll
    for (int o = 1; o < 32; o <<= 1) {
        int u = __shfl_up_sync(0xffffffffu, s, o);
        if (lane >= o) s += u;
    }
    if (lane == 31) ws[w] = s;
    __syncthreads();
    if (w == 0) {
        int u = ws[lane];
#pragma unroll
        for (int o = 1; o < 32; o <<= 1) {
            int x2 = __shfl_up_sync(0xffffffffu, u, o);
            if (lane >= o) u += x2;
        }
        ws[lane] = u;
    }
    __syncthreads();
    int excl = s - v + (w > 0 ? ws[w - 1] : 0);
    if (i < n) off[i] = excl;
    if (t == 1023) bsum[blockIdx.x] = ws[31];
}

// phase 2 — add tile prefix, emit cur=off and total at off[n].
__global__ void k_scan_final(int* __restrict__ off, int* __restrict__ cur,
                             const int* __restrict__ bsum, int nb, int n) {
    __shared__ int pre;
    int b = blockIdx.x, t = threadIdx.x;
    if (t == 0) {
        int s = 0;
        for (int j = 0; j < b; j++) s += bsum[j];
        pre = s;
        if (b == nb - 1) off[n] = s + bsum[b];
    }
    __syncthreads();
    int i = b * 1024 + t;
    if (i < n) {
        int o = off[i] + pre;
        off[i] = o;
        cur[i] = o;
    }
}

__global__ void k_scatter(const int* __restrict__ idx_n, const int* __restrict__ idx_e) {
    int i = blockIdx.x * blockDim.x + threadIdx.x;
    if (i < NI) {
        int p = atomicAdd(&g_cur_n[idx_n[i]], 1);
        g_perm_n[p] = i;
        int q = atomicAdd(&g_cur_e[idx_e[i]], 1);
        g_perm_e[q] = i;
    }
}

// ------------------------- contracted attention vectors -------------------------
__global__ void k_prepw(const float* __restrict__ attW, const float* __restrict__ att) {
    int t = threadIdx.x;       // 0..511
    int h = t / DM, k = t % DM;
    float accn = 0.f, acce = 0.f;
    for (int d = 0; d < DM; d++) {
        float w = attW[(h * DM + d) * DM + k];
        accn += w * att[h * 2 * DM + d];
        acce += w * att[h * 2 * DM + DM + d];
    }
    g_wn[t] = accn;
    g_we[t] = acce;
}

// ------------------------- tf32 tensor-core GEMM -------------------------
// C[M,Nw] = A[M,256] @ W[Nw,256]^T ; block tile 128x128, 8 warps (2m x 4n),
// warp tile 64x32 via mma.m16n8k8 tf32.
// MODE 0: bn1(leaky(acc+bias))  MODE 1: raw  MODE 2: leaky(acc+bias)
template <int MODE>
__global__ void __launch_bounds__(256) k_gemm_mma(
    const float* __restrict__ A, const float* __restrict__ W,
    float* __restrict__ C, int Nw,
    const float* __restrict__ bias,
    const float* __restrict__ bg, const float* __restrict__ bb,
    const float* __restrict__ bm, const float* __restrict__ bv) {
    __shared__ unsigned As[128][36];
    __shared__ unsigned Ws[128][36];
    int tid = threadIdx.x;
    int lane = tid & 31;
    int warp = tid >> 5;
    int wm = warp >> 2;           // 0..1
    int wn = warp & 3;            // 0..3
    int m0 = blockIdx.y * 128;
    int n0 = blockIdx.x * 128;
    int gid = lane >> 2;          // 0..7
    int tig = lane & 3;           // 0..3
    int lrow = tid >> 3;          // 0..31
    int lcol = (tid & 7) * 4;     // 0..28

    float acc[4][4][4];
#pragma unroll
    for (int mt = 0; mt < 4; mt++)
#pragma unroll
        for (int nt = 0; nt < 4; nt++)
#pragma unroll
            for (int c = 0; c < 4; c++) acc[mt][nt][c] = 0.f;

    for (int k0 = 0; k0 < 256; k0 += 32) {
#pragma unroll
        for (int r = 0; r < 4; r++) {
            int row = lrow + r * 32;
            float4 av = *(const float4*)&A[(size_t)(m0 + row) * 256 + k0 + lcol];
            As[row][lcol + 0] = f2tf32(av.x);
            As[row][lcol + 1] = f2tf32(av.y);
            As[row][lcol + 2] = f2tf32(av.z);
            As[row][lcol + 3] = f2tf32(av.w);
            float4 wv = *(const float4*)&W[(size_t)(n0 + row) * 256 + k0 + lcol];
            Ws[row][lcol + 0] = f2tf32(wv.x);
            Ws[row][lcol + 1] = f2tf32(wv.y);
            Ws[row][lcol + 2] = f2tf32(wv.z);
            Ws[row][lcol + 3] = f2tf32(wv.w);
        }
        __syncthreads();
#pragma unroll
        for (int kk = 0; kk < 4; kk++) {
            int kb = kk * 8;
            unsigned af[4][4];
#pragma unroll
            for (int mt = 0; mt < 4; mt++) {
                int r = wm * 64 + mt * 16 + gid;
                af[mt][0] = As[r][kb + tig];
                af[mt][1] = As[r + 8][kb + tig];
                af[mt][2] = As[r][kb + tig + 4];
                af[mt][3] = As[r + 8][kb + tig + 4];
            }
            unsigned bf[4][2];
#pragma unroll
            for (int nt = 0; nt < 4; nt++) {
                int c = wn * 32 + nt * 8 + gid;
                bf[nt][0] = Ws[c][kb + tig];
                bf[nt][1] = Ws[c][kb + tig + 4];
            }
#pragma unroll
            for (int mt = 0; mt < 4; mt++)
#pragma unroll
                for (int nt = 0; nt < 4; nt++) {
                    asm volatile(
                        "mma.sync.aligned.m16n8k8.row.col.f32.tf32.tf32.f32 "
                        "{%0,%1,%2,%3}, {%4,%5,%6,%7}, {%8,%9}, {%0,%1,%2,%3};"
                        : "+f"(acc[mt][nt][0]), "+f"(acc[mt][nt][1]),
                          "+f"(acc[mt][nt][2]), "+f"(acc[mt][nt][3])
                        : "r"(af[mt][0]), "r"(af[mt][1]), "r"(af[mt][2]), "r"(af[mt][3]),
                          "r"(bf[nt][0]), "r"(bf[nt][1]));
                }
        }
        __syncthreads();
    }

    // epilogue
#pragma unroll
    for (int mt = 0; mt < 4; mt++) {
        int row0 = m0 + wm * 64 + mt * 16 + gid;
#pragma unroll
        for (int nt = 0; nt < 4; nt++) {
            int col = n0 + wn * 32 + nt * 8 + tig * 2;
#pragma unroll
            for (int half = 0; half < 2; half++) {
                int row = row0 + half * 8;
                float v0 = acc[mt][nt][half * 2 + 0];
                float v1 = acc[mt][nt][half * 2 + 1];
                if (MODE == 0) {
                    v0 = leaky(v0 + bias[col]);
                    v1 = leaky(v1 + bias[col + 1]);
                    v0 = bg[col] * (v0 - bm[col]) * rsqrtf(bv[col] + EPSV) + bb[col];
                    v1 = bg[col + 1] * (v1 - bm[col + 1]) * rsqrtf(bv[col + 1] + EPSV) + bb[col + 1];
                } else if (MODE == 2) {
                    v0 = leaky(v0 + bias[col]);
                    v1 = leaky(v1 + bias[col + 1]);
                }
                float2 o = make_float2(v0, v1);
                *(float2*)&C[(size_t)row * Nw + col] = o;
            }
        }
    }
}

// ------------------------- edge feature aggregation -------------------------
__global__ void k_eattr(const int* __restrict__ idx_n) {
    int e = blockIdx.x;
    int d = threadIdx.x;   // 256
    int s = g_off_e[e], t = g_off_e[e + 1];
    float acc = 0.f;
    for (int j = s; j < t; j++) {
        int n = idx_n[g_perm_e[j]];
        acc += g_h1[(size_t)n * DM + d];
    }
    g_eattr[(size_t)e * DM + d] = acc;
}

// ------------------------- per-row 2-head dot -------------------------
__global__ void k_dot(const float* __restrict__ X, const float* __restrict__ Wv,
                      float* __restrict__ out, int rows) {
    int gw = (blockIdx.x * blockDim.x + threadIdx.x) / 32;
    int lane = threadIdx.x & 31;
    if (gw >= rows * 2) return;
    int r = gw / 2, h = gw % 2;
    float acc = 0.f;
    for (int k = lane; k < DM; k += 32) acc += X[(size_t)r * DM + k] * Wv[h * DM + k];
#pragma unroll
    for (int o = 16; o > 0; o >>= 1) acc += __shfl_down_sync(0xffffffffu, acc, o);
    if (lane == 0) out[r * 2 + h] = acc;
}

// ------------------------- per-node segment softmax -------------------------
__global__ void k_softmax(const int* __restrict__ idx_e) {
    int n = blockIdx.x * blockDim.x + threadIdx.x;
    if (n >= NN) return;
    int s = g_off_n[n], t = g_off_n[n + 1];
    int deg = t - s;
    g_dinv[n] = deg > 0 ? 1.0f / (float)deg : 0.0f;
    if (deg == 0) return;
    float sn0 = g_sn[n * 2], sn1 = g_sn[n * 2 + 1];
    float m0 = -3.402823e38f, m1 = -3.402823e38f;
    for (int j = s; j < t; j++) {
        int i = g_perm_n[j];
        int e = idx_e[i];
        float a0 = leaky(sn0 + g_se[e * 2]);
        float a1 = leaky(sn1 + g_se[e * 2 + 1]);
        m0 = fmaxf(m0, a0);
        m1 = fmaxf(m1, a1);
    }
    float d0 = 0.f, d1 = 0.f;
    for (int j = s; j < t; j++) {
        int i = g_perm_n[j];
        int e = idx_e[i];
        float e0 = expf(leaky(sn0 + g_se[e * 2]) - m0);
        float e1 = expf(leaky(sn1 + g_se[e * 2 + 1]) - m1);
        d0 += e0;
        d1 += e1;
        g_alpha[i * 2] = e0;
        g_alpha[i * 2 + 1] = e1;
    }
    float r0 = 1.0f / (d0 + 1e-16f);
    float r1 = 1.0f / (d1 + 1e-16f);
    for (int j = s; j < t; j++) {
        int i = g_perm_n[j];
        g_alpha[i * 2] *= r0;
        g_alpha[i * 2 + 1] *= r1;
    }
}

// ------------------------- edge_out[e,h,d] = Binv * sum alpha * xh[n,h,d] -------------------------
__global__ void __launch_bounds__(512) k_edgeout(const int* __restrict__ idx_n) {
    int e = blockIdx.x;
    int t = threadIdx.x;   // 512 : h*256 + d
    int h = t >> 8;
    int s = g_off_e[e], en = g_off_e[e + 1];
    float binv = (en > s) ? 1.0f / (float)(en - s) : 0.0f;
    float acc = 0.f;
    for (int j = s; j < en; j++) {
        int i = g_perm_e[j];
        int n = idx_n[i];
        acc += g_alpha[i * 2 + h] * g_xh[(size_t)n * 512 + t];
    }
    g_edge_out[(size_t)e * 512 + t] = binv * acc;
}

// ------------------------- node_out + mean heads + cb + bn2 -------------------------
__global__ void __launch_bounds__(256) k_nodeout(
    const int* __restrict__ idx_e, const float* __restrict__ cb,
    const float* __restrict__ g2, const float* __restrict__ b2,
    const float* __restrict__ m2, const float* __restrict__ v2) {
    int n = blockIdx.x;
    int d = threadIdx.x;   // 256
    int s = g_off_n[n], t = g_off_n[n + 1];
    float acc0 = 0.f, acc1 = 0.f;
    for (int j = s; j < t; j++) {
        int i = g_perm_n[j];
        int e = idx_e[i];
        acc0 += g_alpha[i * 2] * g_edge_out[(size_t)e * 512 + d];
        acc1 += g_alpha[i * 2 + 1] * g_edge_out[(size_t)e * 512 + 256 + d];
    }
    float x2 = g_dinv[n] * 0.5f * (acc0 + acc1) + cb[d];
    float v = g_h1[(size_t)n * DM + d] + x2;
    v = g2[d] * (v - m2[d]) * rsqrtf(v2[d] + EPSV) + b2[d];
    g_hb[(size_t)n * DM + d] = v;
}

// ------------------------- residual + LayerNorm over 64-chunks -------------------------
__global__ void k_ln(const float* __restrict__ x, const float* __restrict__ h3,
                     const float* __restrict__ lg, const float* __restrict__ lb,
                     float* __restrict__ out) {
    int g = (blockIdx.x * blockDim.x + threadIdx.x) >> 5;   // one warp per 64-group
    int lane = threadIdx.x & 31;
    if (g >= NI) return;   // 131072 groups
    size_t base = (size_t)g * 64;
    float y0 = x[base + lane] + h3[base + lane];
    float y1 = x[base + 32 + lane] + h3[base + 32 + lane];
    float s = y0 + y1;
#pragma unroll
    for (int o = 16; o > 0; o >>= 1) s += __shfl_xor_sync(0xffffffffu, s, o);
    float mu = s * (1.0f / 64.0f);
    float d0 = y0 - mu, d1 = y1 - mu;
    float vv = d0 * d0 + d1 * d1;
#pragma unroll
    for (int o = 16; o > 0; o >>= 1) vv += __shfl_xor_sync(0xffffffffu, vv, o);
    float rs = rsqrtf(vv * (1.0f / 64.0f) + EPSV);
    out[base + lane] = lg[lane] * d0 * rs + lb[lane];
    out[base + 32 + lane] = lg[lane + 32] * d1 * rs + lb[lane + 32];
}

// ------------------------- launch -------------------------
extern "C" void kernel_launch(void* const* d_in, const int* in_sizes, int n_in,
                              void* d_out, int out_size) {
    const float* x    = (const float*)d_in[0];
    const int*   he   = (const int*)d_in[1];
    const int*   idx_n = he;
    const int*   idx_e = he + NI;
    const float* W1   = (const float*)d_in[2];
    const float* b1   = (const float*)d_in[3];
    const float* bn1g = (const float*)d_in[4];
    const float* bn1b = (const float*)d_in[5];
    const float* bn1m = (const float*)d_in[6];
    const float* bn1v = (const float*)d_in[7];
    const float* attW = (const float*)d_in[8];
    const float* att  = (const float*)d_in[9];
    const float* cb   = (const float*)d_in[10];
    const float* bn2g = (const float*)d_in[11];
    const float* bn2b = (const float*)d_in[12];
    const float* bn2m = (const float*)d_in[13];
    const float* bn2v = (const float*)d_in[14];
    const float* W2   = (const float*)d_in[15];
    const float* b2   = (const float*)d_in[16];
    const float* lng  = (const float*)d_in[17];
    const float* lnb  = (const float*)d_in[18];
    float* out = (float*)d_out;

    float *p_h1, *p_xh, *p_eattr, *p_hb, *p_sn, *p_se, *p_wn, *p_we;
    int *p_cnt_n, *p_cnt_e, *p_off_n, *p_off_e, *p_cur_n, *p_cur_e;
    int *p_bsum_n, *p_bsum_e;
    cudaGetSymbolAddress((void**)&p_h1, g_h1);
    cudaGetSymbolAddress((void**)&p_xh, g_xh);
    cudaGetSymbolAddress((void**)&p_eattr, g_eattr);
    cudaGetSymbolAddress((void**)&p_hb, g_hb);
    cudaGetSymbolAddress((void**)&p_sn, g_sn);
    cudaGetSymbolAddress((void**)&p_se, g_se);
    cudaGetSymbolAddress((void**)&p_wn, g_wn);
    cudaGetSymbolAddress((void**)&p_we, g_we);
    cudaGetSymbolAddress((void**)&p_cnt_n, g_cnt_n);
    cudaGetSymbolAddress((void**)&p_cnt_e, g_cnt_e);
    cudaGetSymbolAddress((void**)&p_off_n, g_off_n);
    cudaGetSymbolAddress((void**)&p_off_e, g_off_e);
    cudaGetSymbolAddress((void**)&p_cur_n, g_cur_n);
    cudaGetSymbolAddress((void**)&p_cur_e, g_cur_e);
    cudaGetSymbolAddress((void**)&p_bsum_n, g_bsum_n);
    cudaGetSymbolAddress((void**)&p_bsum_e, g_bsum_e);

    // ---- CSR build ----
    k_zero_int<<<(NN + 255) / 256, 256>>>(p_cnt_n, NN);
    k_zero_int<<<(NE + 255) / 256, 256>>>(p_cnt_e, NE);
    k_hist<<<(NI + 255) / 256, 256>>>(idx_n, idx_e);
    k_scan_local<<<NN / 1024, 1024>>>(p_cnt_n, p_off_n, p_bsum_n, NN);
    k_scan_local<<<NE / 1024, 1024>>>(p_cnt_e, p_off_e, p_bsum_e, NE);
    k_scan_final<<<NN / 1024, 1024>>>(p_off_n, p_cur_n, p_bsum_n, NN / 1024, NN);
    k_scan_final<<<NE / 1024, 1024>>>(p_off_e, p_cur_e, p_bsum_e, NE / 1024, NE);
    k_scatter<<<(NI + 255) / 256, 256>>>(idx_n, idx_e);

    // ---- contracted attention weight vectors ----
    k_prepw<<<1, 512>>>(attW, att);

    // ---- GEMM 1: h1 = bn1(leaky(x @ W1^T + b1)) ----
    {
        dim3 grid(DM / 128, NN / 128);
        k_gemm_mma<0><<<grid, 256>>>(x, W1, p_h1, DM, b1, bn1g, bn1b, bn1m, bn1v);
    }

    // ---- edge features + scores ----
    k_eattr<<<NE, 256>>>(idx_n);
    k_dot<<<(NN * 2 * 32 + 255) / 256, 256>>>(p_h1, p_wn, p_sn, NN);
    k_dot<<<(NE * 2 * 32 + 255) / 256, 256>>>(p_eattr, p_we, p_se, NE);

    // ---- GEMM 2: xh = h1 @ attW^T  [NN, 512] ----
    {
        dim3 grid(512 / 128, NN / 128);
        k_gemm_mma<1><<<grid, 256>>>(p_h1, attW, p_xh, 512, nullptr, nullptr, nullptr, nullptr, nullptr);
    }

    // ---- segment softmax ----
    k_softmax<<<(NN + 255) / 256, 256>>>(idx_e);

    // ---- message passing ----
    k_edgeout<<<NE, 512>>>(idx_n);
    k_nodeout<<<NN, 256>>>(idx_e, cb, bn2g, bn2b, bn2m, bn2v);

    // ---- GEMM 3: h3 = leaky(hb @ W2^T + b2)  (reuse g_xh as h3) ----
    {
        dim3 grid(DM / 128, NN / 128);
        k_gemm_mma<2><<<grid, 256>>>(p_hb, W2, p_xh, DM, b2, nullptr, nullptr, nullptr, nullptr);
    }

    // ---- residual + LayerNorm ----
    k_ln<<<(NI * 32 + 255) / 256, 256>>>(x, p_xh, lng, lnb, out);
}

// round 6
// speedup vs baseline: 2.9656x; 1.3299x over previous
#include <cuda_runtime.h>
#include <math.h>

#define NN 32768
#define NE 4096
#define NI 131072
#define DM 256
#define EPSV 1e-5f
#define NEGS 0.2f

// ------------------------- device scratch -------------------------
__device__ float g_h1[NN * DM];          // post bn1 node features
__device__ float g_eattr[NE * DM];
__device__ float g_agg[2 * NE * DM];     // alpha-weighted h1 aggregate per edge, head-major
__device__ float g_eout[2 * NE * DM];    // edge_out, head-major [h][e][d]
__device__ float g_hb[NN * DM];          // bn2(h1 + x2)
__device__ float g_sn[NN * 2];
__device__ float g_se[NE * 2];
__device__ float g_alpha[NI * 2];
__device__ float g_wn[2 * DM];
__device__ float g_we[2 * DM];
__device__ float g_dinv[NN];
__device__ int g_cnt_n[NN], g_off_n[NN + 1], g_cur_n[NN];
__device__ int g_cnt_e[NE], g_off_e[NE + 1], g_cur_e[NE];
__device__ int g_perm_n[NI], g_perm_e[NI];
__device__ int g_bsum_n[32], g_bsum_e[4];

__device__ __forceinline__ float leaky(float v) { return v >= 0.f ? v : NEGS * v; }

__device__ __forceinline__ unsigned f2tf32(float f) {
    unsigned r;
    asm("cvt.rna.tf32.f32 %0, %1;" : "=r"(r) : "f"(f));
    return r;
}

// ------------------------- CSR build -------------------------
__global__ void k_zero_int(int* a, int n) {
    int i = blockIdx.x * blockDim.x + threadIdx.x;
    if (i < n) a[i] = 0;
}

__global__ void k_hist(const int* __restrict__ idx_n, const int* __restrict__ idx_e) {
    int i = blockIdx.x * blockDim.x + threadIdx.x;
    if (i < NI) {
        atomicAdd(&g_cnt_n[idx_n[i]], 1);
        atomicAdd(&g_cnt_e[idx_e[i]], 1);
    }
}

__global__ void k_scan_local(const int* __restrict__ cnt, int* __restrict__ off,
                             int* __restrict__ bsum, int n) {
    __shared__ int ws[32];
    int t = threadIdx.x;
    int i = blockIdx.x * 1024 + t;
    int v = (i < n) ? cnt[i] : 0;
    int lane = t & 31, w = t >> 5;
    int s = v;
#pragma unroll
    for (int o = 1; o < 32; o <<= 1) {
        int u = __shfl_up_sync(0xffffffffu, s, o);
        if (lane >= o) s += u;
    }
    if (lane == 31) ws[w] = s;
    __syncthreads();
    if (w == 0) {
        int u = ws[lane];
#pragma unroll
        for (int o = 1; o < 32; o <<= 1) {
            int x2 = __shfl_up_sync(0xffffffffu, u, o);
            if (lane >= o) u += x2;
        }
        ws[lane] = u;
    }
    __syncthreads();
    int excl = s - v + (w > 0 ? ws[w - 1] : 0);
    if (i < n) off[i] = excl;
    if (t == 1023) bsum[blockIdx.x] = ws[31];
}

__global__ void k_scan_final(int* __restrict__ off, int* __restrict__ cur,
                             const int* __restrict__ bsum, int nb, int n) {
    __shared__ int pre;
    int b = blockIdx.x, t = threadIdx.x;
    if (t == 0) {
        int s = 0;
        for (int j = 0; j < b; j++) s += bsum[j];
        pre = s;
        if (b == nb - 1) off[n] = s + bsum[b];
    }
    __syncthreads();
    int i = b * 1024 + t;
    if (i < n) {
        int o = off[i] + pre;
        off[i] = o;
        cur[i] = o;
    }
}

__global__ void k_scatter(const int* __restrict__ idx_n, const int* __restrict__ idx_e) {
    int i = blockIdx.x * blockDim.x + threadIdx.x;
    if (i < NI) {
        int p = atomicAdd(&g_cur_n[idx_n[i]], 1);
        g_perm_n[p] = i;
        int q = atomicAdd(&g_cur_e[idx_e[i]], 1);
        g_perm_e[q] = i;
    }
}

// ------------------------- contracted attention vectors -------------------------
__global__ void k_prepw(const float* __restrict__ attW, const float* __restrict__ att) {
    int t = threadIdx.x;       // 0..511
    int h = t / DM, k = t % DM;
    float accn = 0.f, acce = 0.f;
    for (int d = 0; d < DM; d++) {
        float w = attW[(h * DM + d) * DM + k];
        accn += w * att[h * 2 * DM + d];
        acce += w * att[h * 2 * DM + DM + d];
    }
    g_wn[t] = accn;
    g_we[t] = acce;
}

// ------------------------- tf32 tensor-core GEMM -------------------------
// C[M,Nw] = A[M,256] @ W[Nw,256]^T ; block tile 128x128, 8 warps.
// MODE 0: bn1(leaky(acc+bias))
// MODE 1: raw
// MODE 2: leaky(acc+bias)
// MODE 3: y = leaky(acc+bias) + xres(flat) ; LayerNorm over 64-col groups ; write out(flat)
//         (param aliases: bg=ln_g, bb=ln_b, bm=xres)
// blockIdx.z head support via zsA/zsW/zsC element strides.
template <int MODE>
__global__ void __launch_bounds__(256) k_gemm_mma(
    const float* __restrict__ A, const float* __restrict__ W,
    float* __restrict__ C, int Nw,
    const float* __restrict__ bias,
    const float* __restrict__ bg, const float* __restrict__ bb,
    const float* __restrict__ bm, const float* __restrict__ bv,
    size_t zsA, size_t zsW, size_t zsC) {
    __shared__ unsigned As[128][36];
    __shared__ unsigned Ws[128][36];
    A += blockIdx.z * zsA;
    W += blockIdx.z * zsW;
    C += blockIdx.z * zsC;
    int tid = threadIdx.x;
    int lane = tid & 31;
    int warp = tid >> 5;
    int wm = warp >> 2;           // 0..1
    int wn = warp & 3;            // 0..3
    int m0 = blockIdx.y * 128;
    int n0 = blockIdx.x * 128;
    int gid = lane >> 2;          // 0..7
    int tig = lane & 3;           // 0..3
    int lrow = tid >> 3;          // 0..31
    int lcol = (tid & 7) * 4;     // 0..28

    float acc[4][4][4];
#pragma unroll
    for (int mt = 0; mt < 4; mt++)
#pragma unroll
        for (int nt = 0; nt < 4; nt++)
#pragma unroll
            for (int c = 0; c < 4; c++) acc[mt][nt][c] = 0.f;

    for (int k0 = 0; k0 < 256; k0 += 32) {
#pragma unroll
        for (int r = 0; r < 4; r++) {
            int row = lrow + r * 32;
            float4 av = *(const float4*)&A[(size_t)(m0 + row) * 256 + k0 + lcol];
            As[row][lcol + 0] = f2tf32(av.x);
            As[row][lcol + 1] = f2tf32(av.y);
            As[row][lcol + 2] = f2tf32(av.z);
            As[row][lcol + 3] = f2tf32(av.w);
            float4 wv = *(const float4*)&W[(size_t)(n0 + row) * 256 + k0 + lcol];
            Ws[row][lcol + 0] = f2tf32(wv.x);
            Ws[row][lcol + 1] = f2tf32(wv.y);
            Ws[row][lcol + 2] = f2tf32(wv.z);
            Ws[row][lcol + 3] = f2tf32(wv.w);
        }
        __syncthreads();
#pragma unroll
        for (int kk = 0; kk < 4; kk++) {
            int kb = kk * 8;
            unsigned af[4][4];
#pragma unroll
            for (int mt = 0; mt < 4; mt++) {
                int r = wm * 64 + mt * 16 + gid;
                af[mt][0] = As[r][kb + tig];
                af[mt][1] = As[r + 8][kb + tig];
                af[mt][2] = As[r][kb + tig + 4];
                af[mt][3] = As[r + 8][kb + tig + 4];
            }
            unsigned bf[4][2];
#pragma unroll
            for (int nt = 0; nt < 4; nt++) {
                int c = wn * 32 + nt * 8 + gid;
                bf[nt][0] = Ws[c][kb + tig];
                bf[nt][1] = Ws[c][kb + tig + 4];
            }
#pragma unroll
            for (int mt = 0; mt < 4; mt++)
#pragma unroll
                for (int nt = 0; nt < 4; nt++) {
                    asm volatile(
                        "mma.sync.aligned.m16n8k8.row.col.f32.tf32.tf32.f32 "
                        "{%0,%1,%2,%3}, {%4,%5,%6,%7}, {%8,%9}, {%0,%1,%2,%3};"
                        : "+f"(acc[mt][nt][0]), "+f"(acc[mt][nt][1]),
                          "+f"(acc[mt][nt][2]), "+f"(acc[mt][nt][3])
                        : "r"(af[mt][0]), "r"(af[mt][1]), "r"(af[mt][2]), "r"(af[mt][3]),
                          "r"(bf[nt][0]), "r"(bf[nt][1]));
                }
        }
        __syncthreads();
    }

    if (MODE == 3) {
        // y = leaky(acc + bias) + x(flat) ; LN over 64-column groups (2 per block).
        // The reference's reshape is a flat reinterpretation: element (m, col) of the
        // GEMM output aligns with flat index m*256 + col of both xres and out.
        float* sred = (float*)&As[0][0];     // [128 rows][2 grp][2 {s,ss}]
        for (int i = tid; i < 128 * 2 * 2; i += 256) sred[i] = 0.f;
        __syncthreads();
        int grp = wn >> 1;
        const float* xres = bm;
#pragma unroll
        for (int mt = 0; mt < 4; mt++) {
#pragma unroll
            for (int half = 0; half < 2; half++) {
                int rloc = wm * 64 + mt * 16 + gid + half * 8;
                int m = m0 + rloc;
                float s = 0.f, ss = 0.f;
#pragma unroll
                for (int nt = 0; nt < 4; nt++) {
                    int col = n0 + wn * 32 + nt * 8 + tig * 2;
                    size_t fi = (size_t)m * 256 + col;
                    float2 xv = *(const float2*)&xres[fi];
                    float y0 = leaky(acc[mt][nt][half * 2 + 0] + bias[col]) + xv.x;
                    float y1 = leaky(acc[mt][nt][half * 2 + 1] + bias[col + 1]) + xv.y;
                    acc[mt][nt][half * 2 + 0] = y0;
                    acc[mt][nt][half * 2 + 1] = y1;
                    s += y0 + y1;
                    ss += y0 * y0 + y1 * y1;
                }
                s += __shfl_xor_sync(0xffffffffu, s, 1);
                ss += __shfl_xor_sync(0xffffffffu, ss, 1);
                s += __shfl_xor_sync(0xffffffffu, s, 2);
                ss += __shfl_xor_sync(0xffffffffu, ss, 2);
                if (tig == 0) {
                    atomicAdd(&sred[(rloc * 2 + grp) * 2 + 0], s);
                    atomicAdd(&sred[(rloc * 2 + grp) * 2 + 1], ss);
                }
            }
        }
        __syncthreads();
#pragma unroll
        for (int mt = 0; mt < 4; mt++) {
#pragma unroll
            for (int half = 0; half < 2; half++) {
                int rloc = wm * 64 + mt * 16 + gid + half * 8;
                int m = m0 + rloc;
                float s = sred[(rloc * 2 + grp) * 2 + 0];
                float ss = sred[(rloc * 2 + grp) * 2 + 1];
                float mu = s * (1.0f / 64.0f);
                float var = ss * (1.0f / 64.0f) - mu * mu;
                float rs = rsqrtf(var + EPSV);
#pragma unroll
                for (int nt = 0; nt < 4; nt++) {
                    int col = n0 + wn * 32 + nt * 8 + tig * 2;
                    int c = col & 63;
                    float y0 = acc[mt][nt][half * 2 + 0];
                    float y1 = acc[mt][nt][half * 2 + 1];
                    float2 o = make_float2(bg[c] * (y0 - mu) * rs + bb[c],
                                           bg[c + 1] * (y1 - mu) * rs + bb[c + 1]);
                    *(float2*)&C[(size_t)m * 256 + col] = o;
                }
            }
        }
        return;
    }

    // epilogue (MODE 0/1/2)
#pragma unroll
    for (int mt = 0; mt < 4; mt++) {
        int row0 = m0 + wm * 64 + mt * 16 + gid;
#pragma unroll
        for (int nt = 0; nt < 4; nt++) {
            int col = n0 + wn * 32 + nt * 8 + tig * 2;
#pragma unroll
            for (int half = 0; half < 2; half++) {
                int row = row0 + half * 8;
                float v0 = acc[mt][nt][half * 2 + 0];
                float v1 = acc[mt][nt][half * 2 + 1];
                if (MODE == 0) {
                    v0 = leaky(v0 + bias[col]);
                    v1 = leaky(v1 + bias[col + 1]);
                    v0 = bg[col] * (v0 - bm[col]) * rsqrtf(bv[col] + EPSV) + bb[col];
                    v1 = bg[col + 1] * (v1 - bm[col + 1]) * rsqrtf(bv[col + 1] + EPSV) + bb[col + 1];
                } else if (MODE == 2) {
                    v0 = leaky(v0 + bias[col]);
                    v1 = leaky(v1 + bias[col + 1]);
                }
                float2 o = make_float2(v0, v1);
                *(float2*)&C[(size_t)row * Nw + col] = o;
            }
        }
    }
}

// ------------------------- edge feature aggregation (unweighted) -------------------------
__global__ void k_eattr(const int* __restrict__ idx_n) {
    int e = blockIdx.x;
    int d = threadIdx.x;   // 256
    int s = g_off_e[e], t = g_off_e[e + 1];
    float acc = 0.f;
    for (int j = s; j < t; j++) {
        int n = idx_n[g_perm_e[j]];
        acc += g_h1[(size_t)n * DM + d];
    }
    g_eattr[(size_t)e * DM + d] = acc;
}

// ------------------------- per-row 2-head dot -------------------------
__global__ void k_dot(const float* __restrict__ X, const float* __restrict__ Wv,
                      float* __restrict__ out, int rows) {
    int gw = (blockIdx.x * blockDim.x + threadIdx.x) / 32;
    int lane = threadIdx.x & 31;
    if (gw >= rows * 2) return;
    int r = gw / 2, h = gw % 2;
    float acc = 0.f;
    for (int k = lane; k < DM; k += 32) acc += X[(size_t)r * DM + k] * Wv[h * DM + k];
#pragma unroll
    for (int o = 16; o > 0; o >>= 1) acc += __shfl_down_sync(0xffffffffu, acc, o);
    if (lane == 0) out[r * 2 + h] = acc;
}

// ------------------------- per-node segment softmax -------------------------
__global__ void k_softmax(const int* __restrict__ idx_e) {
    int n = blockIdx.x * blockDim.x + threadIdx.x;
    if (n >= NN) return;
    int s = g_off_n[n], t = g_off_n[n + 1];
    int deg = t - s;
    g_dinv[n] = deg > 0 ? 1.0f / (float)deg : 0.0f;
    if (deg == 0) return;
    float sn0 = g_sn[n * 2], sn1 = g_sn[n * 2 + 1];
    float m0 = -3.402823e38f, m1 = -3.402823e38f;
    for (int j = s; j < t; j++) {
        int i = g_perm_n[j];
        int e = idx_e[i];
        float a0 = leaky(sn0 + g_se[e * 2]);
        float a1 = leaky(sn1 + g_se[e * 2 + 1]);
        m0 = fmaxf(m0, a0);
        m1 = fmaxf(m1, a1);
    }
    float d0 = 0.f, d1 = 0.f;
    for (int j = s; j < t; j++) {
        int i = g_perm_n[j];
        int e = idx_e[i];
        float e0 = expf(leaky(sn0 + g_se[e * 2]) - m0);
        float e1 = expf(leaky(sn1 + g_se[e * 2 + 1]) - m1);
        d0 += e0;
        d1 += e1;
        g_alpha[i * 2] = e0;
        g_alpha[i * 2 + 1] = e1;
    }
    float r0 = 1.0f / (d0 + 1e-16f);
    float r1 = 1.0f / (d1 + 1e-16f);
    for (int j = s; j < t; j++) {
        int i = g_perm_n[j];
        g_alpha[i * 2] *= r0;
        g_alpha[i * 2 + 1] *= r1;
    }
}

// ------------------------- alpha-weighted edge aggregation (both heads, one pass) ----
// agg[h][e][d] = Binv(e) * sum_i alpha[i,h] * h1[n_i, d]
__global__ void __launch_bounds__(256) k_agg(const int* __restrict__ idx_n) {
    int e = blockIdx.x;
    int d = threadIdx.x;   // 256
    int s = g_off_e[e], t = g_off_e[e + 1];
    float binv = (t > s) ? 1.0f / (float)(t - s) : 0.0f;
    float a0 = 0.f, a1 = 0.f;
    for (int j = s; j < t; j++) {
        int i = g_perm_e[j];
        int n = idx_n[i];
        float v = g_h1[(size_t)n * DM + d];
        a0 += g_alpha[i * 2] * v;
        a1 += g_alpha[i * 2 + 1] * v;
    }
    g_agg[(size_t)e * DM + d] = binv * a0;
    g_agg[(size_t)(NE + e) * DM + d] = binv * a1;
}

// ------------------------- node_out + mean heads + cb + bn2 -------------------------
__global__ void __launch_bounds__(256) k_nodeout(
    const int* __restrict__ idx_e, const float* __restrict__ cb,
    const float* __restrict__ g2, const float* __restrict__ b2,
    const float* __restrict__ m2, const float* __restrict__ v2) {
    int n = blockIdx.x;
    int d = threadIdx.x;   // 256
    int s = g_off_n[n], t = g_off_n[n + 1];
    float acc0 = 0.f, acc1 = 0.f;
    for (int j = s; j < t; j++) {
        int i = g_perm_n[j];
        int e = idx_e[i];
        acc0 += g_alpha[i * 2] * g_eout[(size_t)e * DM + d];
        acc1 += g_alpha[i * 2 + 1] * g_eout[(size_t)(NE + e) * DM + d];
    }
    float x2 = g_dinv[n] * 0.5f * (acc0 + acc1) + cb[d];
    float v = g_h1[(size_t)n * DM + d] + x2;
    v = g2[d] * (v - m2[d]) * rsqrtf(v2[d] + EPSV) + b2[d];
    g_hb[(size_t)n * DM + d] = v;
}

// ------------------------- launch -------------------------
extern "C" void kernel_launch(void* const* d_in, const int* in_sizes, int n_in,
                              void* d_out, int out_size) {
    const float* x    = (const float*)d_in[0];
    const int*   he   = (const int*)d_in[1];
    const int*   idx_n = he;
    const int*   idx_e = he + NI;
    const float* W1   = (const float*)d_in[2];
    const float* b1   = (const float*)d_in[3];
    const float* bn1g = (const float*)d_in[4];
    const float* bn1b = (const float*)d_in[5];
    const float* bn1m = (const float*)d_in[6];
    const float* bn1v = (const float*)d_in[7];
    const float* attW = (const float*)d_in[8];
    const float* att  = (const float*)d_in[9];
    const float* cb   = (const float*)d_in[10];
    const float* bn2g = (const float*)d_in[11];
    const float* bn2b = (const float*)d_in[12];
    const float* bn2m = (const float*)d_in[13];
    const float* bn2v = (const float*)d_in[14];
    const float* W2   = (const float*)d_in[15];
    const float* b2   = (const float*)d_in[16];
    const float* lng  = (const float*)d_in[17];
    const float* lnb  = (const float*)d_in[18];
    float* out = (float*)d_out;

    float *p_h1, *p_eattr, *p_agg, *p_eout, *p_hb, *p_sn, *p_se, *p_wn, *p_we;
    int *p_cnt_n, *p_cnt_e, *p_off_n, *p_off_e, *p_cur_n, *p_cur_e;
    int *p_bsum_n, *p_bsum_e;
    cudaGetSymbolAddress((void**)&p_h1, g_h1);
    cudaGetSymbolAddress((void**)&p_eattr, g_eattr);
    cudaGetSymbolAddress((void**)&p_agg, g_agg);
    cudaGetSymbolAddress((void**)&p_eout, g_eout);
    cudaGetSymbolAddress((void**)&p_hb, g_hb);
    cudaGetSymbolAddress((void**)&p_sn, g_sn);
    cudaGetSymbolAddress((void**)&p_se, g_se);
    cudaGetSymbolAddress((void**)&p_wn, g_wn);
    cudaGetSymbolAddress((void**)&p_we, g_we);
    cudaGetSymbolAddress((void**)&p_cnt_n, g_cnt_n);
    cudaGetSymbolAddress((void**)&p_cnt_e, g_cnt_e);
    cudaGetSymbolAddress((void**)&p_off_n, g_off_n);
    cudaGetSymbolAddress((void**)&p_off_e, g_off_e);
    cudaGetSymbolAddress((void**)&p_cur_n, g_cur_n);
    cudaGetSymbolAddress((void**)&p_cur_e, g_cur_e);
    cudaGetSymbolAddress((void**)&p_bsum_n, g_bsum_n);
    cudaGetSymbolAddress((void**)&p_bsum_e, g_bsum_e);

    // ---- CSR build ----
    k_zero_int<<<(NN + 255) / 256, 256>>>(p_cnt_n, NN);
    k_zero_int<<<(NE + 255) / 256, 256>>>(p_cnt_e, NE);
    k_hist<<<(NI + 255) / 256, 256>>>(idx_n, idx_e);
    k_scan_local<<<NN / 1024, 1024>>>(p_cnt_n, p_off_n, p_bsum_n, NN);
    k_scan_local<<<NE / 1024, 1024>>>(p_cnt_e, p_off_e, p_bsum_e, NE);
    k_scan_final<<<NN / 1024, 1024>>>(p_off_n, p_cur_n, p_bsum_n, NN / 1024, NN);
    k_scan_final<<<NE / 1024, 1024>>>(p_off_e, p_cur_e, p_bsum_e, NE / 1024, NE);
    k_scatter<<<(NI + 255) / 256, 256>>>(idx_n, idx_e);

    // ---- contracted attention weight vectors ----
    k_prepw<<<1, 512>>>(attW, att);

    // ---- GEMM 1: h1 = bn1(leaky(x @ W1^T + b1)) ----
    {
        dim3 grid(DM / 128, NN / 128, 1);
        k_gemm_mma<0><<<grid, 256>>>(x, W1, p_h1, DM, b1, bn1g, bn1b, bn1m, bn1v, 0, 0, 0);
    }

    // ---- edge features + scores ----
    k_eattr<<<NE, 256>>>(idx_n);
    k_dot<<<(NN * 2 * 32 + 255) / 256, 256>>>(p_h1, p_wn, p_sn, NN);
    k_dot<<<(NE * 2 * 32 + 255) / 256, 256>>>(p_eattr, p_we, p_se, NE);

    // ---- segment softmax ----
    k_softmax<<<(NN + 255) / 256, 256>>>(idx_e);

    // ---- alpha-weighted aggregation (replaces xh GEMM + edge gather) ----
    k_agg<<<NE, 256>>>(idx_n);

    // ---- edge GEMM: eout[h] = agg[h] @ attW_h^T  (tiny: 2 x [4096,256,256]) ----
    {
        dim3 grid(DM / 128, NE / 128, 2);
        k_gemm_mma<1><<<grid, 256>>>(p_agg, attW, p_eout, DM,
                                     nullptr, nullptr, nullptr, nullptr, nullptr,
                                     (size_t)NE * DM, (size_t)DM * DM, (size_t)NE * DM);
    }

    // ---- node aggregation + bn2 ----
    k_nodeout<<<NN, 256>>>(idx_e, cb, bn2g, bn2b, bn2m, bn2v);

    // ---- GEMM 3 fused with residual + LayerNorm: out = LN(x + leaky(hb @ W2^T + b2)) ----
    {
        dim3 grid(DM / 128, NN / 128, 1);
        k_gemm_mma<3><<<grid, 256>>>(p_hb, W2, out, DM, b2, lng, lnb, x, nullptr, 0, 0, 0);
    }
}

// round 7
// speedup vs baseline: 3.2290x; 1.0888x over previous
#include <cuda_runtime.h>
#include <math.h>

#define NN 32768
#define NE 4096
#define NI 131072
#define DM 256
#define EPSV 1e-5f
#define NEGS 0.2f

// ------------------------- device scratch -------------------------
__device__ float g_h1[NN * DM];          // post bn1 node features
__device__ float g_agg[2 * NE * DM];     // alpha-weighted h1 aggregate per edge, head-major
__device__ float g_eout[2 * NE * DM];    // edge_out, head-major [h][e][d]
__device__ float g_hb[NN * DM];          // bn2(h1 + x2)
__device__ float g_sn[NN * 2];
__device__ float g_tn[NN * 2];           // h1 . w_e  (per node, per head)
__device__ float g_se[NE * 2];
__device__ float g_alpha[NI * 2];
__device__ float g_wn[2 * DM];
__device__ float g_we[2 * DM];
__device__ float g_dinv[NN];
__device__ int g_cnt_n[NN], g_off_n[NN + 1], g_cur_n[NN];
__device__ int g_cnt_e[NE], g_off_e[NE + 1], g_cur_e[NE];
__device__ int g_perm_n[NI], g_perm_e[NI];
__device__ int g_bsum_n[32], g_bsum_e[4];

__device__ __forceinline__ float leaky(float v) { return v >= 0.f ? v : NEGS * v; }

__device__ __forceinline__ void cp16(void* dst, const void* src) {
    unsigned d = (unsigned)__cvta_generic_to_shared(dst);
    asm volatile("cp.async.cg.shared.global [%0], [%1], 16;" :: "r"(d), "l"(src) : "memory");
}

// ------------------------- CSR build -------------------------
__global__ void k_zero_int(int* a, int n) {
    int i = blockIdx.x * blockDim.x + threadIdx.x;
    if (i < n) a[i] = 0;
}

__global__ void k_hist(const int* __restrict__ idx_n, const int* __restrict__ idx_e) {
    int i = blockIdx.x * blockDim.x + threadIdx.x;
    if (i < NI) {
        atomicAdd(&g_cnt_n[idx_n[i]], 1);
        atomicAdd(&g_cnt_e[idx_e[i]], 1);
    }
}

__global__ void k_scan_local(const int* __restrict__ cnt, int* __restrict__ off,
                             int* __restrict__ bsum, int n) {
    __shared__ int ws[32];
    int t = threadIdx.x;
    int i = blockIdx.x * 1024 + t;
    int v = (i < n) ? cnt[i] : 0;
    int lane = t & 31, w = t >> 5;
    int s = v;
#pragma unroll
    for (int o = 1; o < 32; o <<= 1) {
        int u = __shfl_up_sync(0xffffffffu, s, o);
        if (lane >= o) s += u;
    }
    if (lane == 31) ws[w] = s;
    __syncthreads();
    if (w == 0) {
        int u = ws[lane];
#pragma unroll
        for (int o = 1; o < 32; o <<= 1) {
            int x2 = __shfl_up_sync(0xffffffffu, u, o);
            if (lane >= o) u += x2;
        }
        ws[lane] = u;
    }
    __syncthreads();
    int excl = s - v + (w > 0 ? ws[w - 1] : 0);
    if (i < n) off[i] = excl;
    if (t == 1023) bsum[blockIdx.x] = ws[31];
}

__global__ void k_scan_final(int* __restrict__ off, int* __restrict__ cur,
                             const int* __restrict__ bsum, int nb, int n) {
    __shared__ int pre;
    int b = blockIdx.x, t = threadIdx.x;
    if (t == 0) {
        int s = 0;
        for (int j = 0; j < b; j++) s += bsum[j];
        pre = s;
        if (b == nb - 1) off[n] = s + bsum[b];
    }
    __syncthreads();
    int i = b * 1024 + t;
    if (i < n) {
        int o = off[i] + pre;
        off[i] = o;
        cur[i] = o;
    }
}

__global__ void k_scatter(const int* __restrict__ idx_n, const int* __restrict__ idx_e) {
    int i = blockIdx.x * blockDim.x + threadIdx.x;
    if (i < NI) {
        int p = atomicAdd(&g_cur_n[idx_n[i]], 1);
        g_perm_n[p] = i;
        int q = atomicAdd(&g_cur_e[idx_e[i]], 1);
        g_perm_e[q] = i;
    }
}

// ------------------------- contracted attention vectors -------------------------
__global__ void k_prepw(const float* __restrict__ attW, const float* __restrict__ att) {
    int t = threadIdx.x;       // 0..511
    int h = t / DM, k = t % DM;
    float accn = 0.f, acce = 0.f;
    for (int d = 0; d < DM; d++) {
        float w = attW[(h * DM + d) * DM + k];
        accn += w * att[h * 2 * DM + d];
        acce += w * att[h * 2 * DM + DM + d];
    }
    g_wn[t] = accn;
    g_we[t] = acce;
}

// ------------------------- tf32 tensor-core GEMM, cp.async 2-stage ---------------
// C[M,Nw] = A[M,256] @ W[Nw,256]^T ; block tile 128x128, 8 warps.
// MODE 0: bn1(leaky(acc+bias))
// MODE 1: raw
// MODE 3: y = leaky(acc+bias) + xres(flat) ; LayerNorm over 64-col groups ; write out(flat)
//         (param aliases: bg=ln_g, bb=ln_b, bm=xres)
// blockIdx.z head support via zsA/zsW/zsC element strides.
// Inputs are raw f32 in smem; mma.tf32 truncates to tf32 (RZ) in hardware.
template <int MODE>
__global__ void __launch_bounds__(256) k_gemm_mma(
    const float* __restrict__ A, const float* __restrict__ W,
    float* __restrict__ C, int Nw,
    const float* __restrict__ bias,
    const float* __restrict__ bg, const float* __restrict__ bb,
    const float* __restrict__ bm, const float* __restrict__ bv,
    size_t zsA, size_t zsW, size_t zsC) {
    // k-chunk 16, rows padded to 20 floats (80B = 16B-aligned, conflict-free banks)
    __shared__ alignas(16) float As[2][128][20];
    __shared__ alignas(16) float Ws[2][128][20];
    A += blockIdx.z * zsA;
    W += blockIdx.z * zsW;
    C += blockIdx.z * zsC;
    int tid = threadIdx.x;
    int lane = tid & 31;
    int warp = tid >> 5;
    int wm = warp >> 2;           // 0..1
    int wn = warp & 3;            // 0..3
    int m0 = blockIdx.y * 128;
    int n0 = blockIdx.x * 128;
    int gid = lane >> 2;          // 0..7
    int tig = lane & 3;           // 0..3

    float acc[4][4][4];
#pragma unroll
    for (int mt = 0; mt < 4; mt++)
#pragma unroll
        for (int nt = 0; nt < 4; nt++)
#pragma unroll
            for (int c = 0; c < 4; c++) acc[mt][nt][c] = 0.f;

    // per-thread cp.async assignment: 128 rows x 4 chunks(16B) per matrix
    int r0 = tid >> 2;               // 0..63
    int c0 = (tid & 3) << 2;         // 0,4,8,12

    // issue chunk kc into stage st
    auto issue_tile = [&](int kc, int st) {
        cp16(&As[st][r0][c0], &A[(size_t)(m0 + r0) * 256 + kc + c0]);
        cp16(&As[st][r0 + 64][c0], &A[(size_t)(m0 + r0 + 64) * 256 + kc + c0]);
        cp16(&Ws[st][r0][c0], &W[(size_t)(n0 + r0) * 256 + kc + c0]);
        cp16(&Ws[st][r0 + 64][c0], &W[(size_t)(n0 + r0 + 64) * 256 + kc + c0]);
        asm volatile("cp.async.commit_group;" ::: "memory");
    };

    issue_tile(0, 0);
#pragma unroll 4
    for (int it = 0; it < 16; it++) {
        int st = it & 1;
        if (it < 15) {
            issue_tile((it + 1) * 16, st ^ 1);
            asm volatile("cp.async.wait_group 1;" ::: "memory");
        } else {
            asm volatile("cp.async.wait_group 0;" ::: "memory");
        }
        __syncthreads();
#pragma unroll
        for (int kk = 0; kk < 2; kk++) {
            int kb = kk * 8;
            unsigned af[4][4];
#pragma unroll
            for (int mt = 0; mt < 4; mt++) {
                int r = wm * 64 + mt * 16 + gid;
                af[mt][0] = __float_as_uint(As[st][r][kb + tig]);
                af[mt][1] = __float_as_uint(As[st][r + 8][kb + tig]);
                af[mt][2] = __float_as_uint(As[st][r][kb + tig + 4]);
                af[mt][3] = __float_as_uint(As[st][r + 8][kb + tig + 4]);
            }
            unsigned bf[4][2];
#pragma unroll
            for (int nt = 0; nt < 4; nt++) {
                int c = wn * 32 + nt * 8 + gid;
                bf[nt][0] = __float_as_uint(Ws[st][c][kb + tig]);
                bf[nt][1] = __float_as_uint(Ws[st][c][kb + tig + 4]);
            }
#pragma unroll
            for (int mt = 0; mt < 4; mt++)
#pragma unroll
                for (int nt = 0; nt < 4; nt++) {
                    asm volatile(
                        "mma.sync.aligned.m16n8k8.row.col.f32.tf32.tf32.f32 "
                        "{%0,%1,%2,%3}, {%4,%5,%6,%7}, {%8,%9}, {%0,%1,%2,%3};"
                        : "+f"(acc[mt][nt][0]), "+f"(acc[mt][nt][1]),
                          "+f"(acc[mt][nt][2]), "+f"(acc[mt][nt][3])
                        : "r"(af[mt][0]), "r"(af[mt][1]), "r"(af[mt][2]), "r"(af[mt][3]),
                          "r"(bf[nt][0]), "r"(bf[nt][1]));
                }
        }
        __syncthreads();
    }

    if (MODE == 3) {
        // y = leaky(acc + bias) + x(flat) ; LN over 64-column groups (2 per block).
        float* sred = &As[0][0][0];     // [128 rows][2 grp][2 {s,ss}]
        for (int i = tid; i < 128 * 2 * 2; i += 256) sred[i] = 0.f;
        __syncthreads();
        int grp = wn >> 1;
        const float* xres = bm;
#pragma unroll
        for (int mt = 0; mt < 4; mt++) {
#pragma unroll
            for (int half = 0; half < 2; half++) {
                int rloc = wm * 64 + mt * 16 + gid + half * 8;
                int m = m0 + rloc;
                float s = 0.f, ss = 0.f;
#pragma unroll
                for (int nt = 0; nt < 4; nt++) {
                    int col = n0 + wn * 32 + nt * 8 + tig * 2;
                    size_t fi = (size_t)m * 256 + col;
                    float2 xv = *(const float2*)&xres[fi];
                    float y0 = leaky(acc[mt][nt][half * 2 + 0] + bias[col]) + xv.x;
                    float y1 = leaky(acc[mt][nt][half * 2 + 1] + bias[col + 1]) + xv.y;
                    acc[mt][nt][half * 2 + 0] = y0;
                    acc[mt][nt][half * 2 + 1] = y1;
                    s += y0 + y1;
                    ss += y0 * y0 + y1 * y1;
                }
                s += __shfl_xor_sync(0xffffffffu, s, 1);
                ss += __shfl_xor_sync(0xffffffffu, ss, 1);
                s += __shfl_xor_sync(0xffffffffu, s, 2);
                ss += __shfl_xor_sync(0xffffffffu, ss, 2);
                if (tig == 0) {
                    atomicAdd(&sred[(rloc * 2 + grp) * 2 + 0], s);
                    atomicAdd(&sred[(rloc * 2 + grp) * 2 + 1], ss);
                }
            }
        }
        __syncthreads();
#pragma unroll
        for (int mt = 0; mt < 4; mt++) {
#pragma unroll
            for (int half = 0; half < 2; half++) {
                int rloc = wm * 64 + mt * 16 + gid + half * 8;
                int m = m0 + rloc;
                float s = sred[(rloc * 2 + grp) * 2 + 0];
                float ss = sred[(rloc * 2 + grp) * 2 + 1];
                float mu = s * (1.0f / 64.0f);
                float var = ss * (1.0f / 64.0f) - mu * mu;
                float rs = rsqrtf(var + EPSV);
#pragma unroll
                for (int nt = 0; nt < 4; nt++) {
                    int col = n0 + wn * 32 + nt * 8 + tig * 2;
                    int c = col & 63;
                    float y0 = acc[mt][nt][half * 2 + 0];
                    float y1 = acc[mt][nt][half * 2 + 1];
                    float2 o = make_float2(bg[c] * (y0 - mu) * rs + bb[c],
                                           bg[c + 1] * (y1 - mu) * rs + bb[c + 1]);
                    *(float2*)&C[(size_t)m * 256 + col] = o;
                }
            }
        }
        return;
    }

    // epilogue (MODE 0/1)
#pragma unroll
    for (int mt = 0; mt < 4; mt++) {
        int row0 = m0 + wm * 64 + mt * 16 + gid;
#pragma unroll
        for (int nt = 0; nt < 4; nt++) {
            int col = n0 + wn * 32 + nt * 8 + tig * 2;
#pragma unroll
            for (int half = 0; half < 2; half++) {
                int row = row0 + half * 8;
                float v0 = acc[mt][nt][half * 2 + 0];
                float v1 = acc[mt][nt][half * 2 + 1];
                if (MODE == 0) {
                    v0 = leaky(v0 + bias[col]);
                    v1 = leaky(v1 + bias[col + 1]);
                    v0 = bg[col] * (v0 - bm[col]) * rsqrtf(bv[col] + EPSV) + bb[col];
                    v1 = bg[col + 1] * (v1 - bm[col + 1]) * rsqrtf(bv[col + 1] + EPSV) + bb[col + 1];
                }
                float2 o = make_float2(v0, v1);
                *(float2*)&C[(size_t)row * Nw + col] = o;
            }
        }
    }
}

// ------------------------- per-node dual dots: sn = h1.wn, tn = h1.we ----------
__global__ void __launch_bounds__(256) k_dot2() {
    __shared__ float w[4][DM];
    int tid = threadIdx.x;
    for (int i = tid; i < 4 * DM; i += 256) {
        int a = i >> 8, k = i & 255;
        w[a][k] = (a < 2) ? g_wn[a * DM + k] : g_we[(a - 2) * DM + k];
    }
    __syncthreads();
    int warp = tid >> 5, lane = tid & 31;
    int n = blockIdx.x * 8 + warp;
    int kb = lane * 8;
    float4 v0 = *(const float4*)&g_h1[(size_t)n * DM + kb];
    float4 v1 = *(const float4*)&g_h1[(size_t)n * DM + kb + 4];
    float acc[4];
#pragma unroll
    for (int a = 0; a < 4; a++) {
        const float* wa = &w[a][kb];
        acc[a] = v0.x * wa[0] + v0.y * wa[1] + v0.z * wa[2] + v0.w * wa[3]
               + v1.x * wa[4] + v1.y * wa[5] + v1.z * wa[6] + v1.w * wa[7];
#pragma unroll
        for (int o = 16; o; o >>= 1) acc[a] += __shfl_xor_sync(0xffffffffu, acc[a], o);
    }
    if (lane == 0) {
        g_sn[n * 2] = acc[0];
        g_sn[n * 2 + 1] = acc[1];
        g_tn[n * 2] = acc[2];
        g_tn[n * 2 + 1] = acc[3];
    }
}

// ------------------------- se[e,h] = sum_i tn[n_i,h]  (scalar segment sum) ------
__global__ void k_se(const int* __restrict__ idx_n) {
    int gw = (blockIdx.x * blockDim.x + threadIdx.x) >> 5;
    int lane = threadIdx.x & 31;
    if (gw >= NE) return;
    int s = g_off_e[gw], t = g_off_e[gw + 1];
    float a0 = 0.f, a1 = 0.f;
    for (int j = s + lane; j < t; j += 32) {
        int n = idx_n[g_perm_e[j]];
        a0 += g_tn[n * 2];
        a1 += g_tn[n * 2 + 1];
    }
#pragma unroll
    for (int o = 16; o; o >>= 1) {
        a0 += __shfl_xor_sync(0xffffffffu, a0, o);
        a1 += __shfl_xor_sync(0xffffffffu, a1, o);
    }
    if (lane == 0) {
        g_se[gw * 2] = a0;
        g_se[gw * 2 + 1] = a1;
    }
}

// ------------------------- per-node segment softmax -------------------------
__global__ void k_softmax(const int* __restrict__ idx_e) {
    int n = blockIdx.x * blockDim.x + threadIdx.x;
    if (n >= NN) return;
    int s = g_off_n[n], t = g_off_n[n + 1];
    int deg = t - s;
    g_dinv[n] = deg > 0 ? 1.0f / (float)deg : 0.0f;
    if (deg == 0) return;
    float sn0 = g_sn[n * 2], sn1 = g_sn[n * 2 + 1];
    float m0 = -3.402823e38f, m1 = -3.402823e38f;
    for (int j = s; j < t; j++) {
        int i = g_perm_n[j];
        int e = idx_e[i];
        float a0 = leaky(sn0 + g_se[e * 2]);
        float a1 = leaky(sn1 + g_se[e * 2 + 1]);
        m0 = fmaxf(m0, a0);
        m1 = fmaxf(m1, a1);
    }
    float d0 = 0.f, d1 = 0.f;
    for (int j = s; j < t; j++) {
        int i = g_perm_n[j];
        int e = idx_e[i];
        float e0 = expf(leaky(sn0 + g_se[e * 2]) - m0);
        float e1 = expf(leaky(sn1 + g_se[e * 2 + 1]) - m1);
        d0 += e0;
        d1 += e1;
        g_alpha[i * 2] = e0;
        g_alpha[i * 2 + 1] = e1;
    }
    float r0 = 1.0f / (d0 + 1e-16f);
    float r1 = 1.0f / (d1 + 1e-16f);
    for (int j = s; j < t; j++) {
        int i = g_perm_n[j];
        g_alpha[i * 2] *= r0;
        g_alpha[i * 2 + 1] *= r1;
    }
}

// ------------------------- alpha-weighted edge aggregation (both heads, one pass) ----
// agg[h][e][d] = Binv(e) * sum_i alpha[i,h] * h1[n_i, d]
__global__ void __launch_bounds__(256) k_agg(const int* __restrict__ idx_n) {
    int e = blockIdx.x;
    int d = threadIdx.x;   // 256
    int s = g_off_e[e], t = g_off_e[e + 1];
    float binv = (t > s) ? 1.0f / (float)(t - s) : 0.0f;
    float a0 = 0.f, a1 = 0.f;
    for (int j = s; j < t; j++) {
        int i = g_perm_e[j];
        int n = idx_n[i];
        float v = g_h1[(size_t)n * DM + d];
        a0 += g_alpha[i * 2] * v;
        a1 += g_alpha[i * 2 + 1] * v;
    }
    g_agg[(size_t)e * DM + d] = binv * a0;
    g_agg[(size_t)(NE + e) * DM + d] = binv * a1;
}

// ------------------------- node_out + mean heads + cb + bn2 -------------------------
__global__ void __launch_bounds__(256) k_nodeout(
    const int* __restrict__ idx_e, const float* __restrict__ cb,
    const float* __restrict__ g2, const float* __restrict__ b2,
    const float* __restrict__ m2, const float* __restrict__ v2) {
    int n = blockIdx.x;
    int d = threadIdx.x;   // 256
    int s = g_off_n[n], t = g_off_n[n + 1];
    float acc0 = 0.f, acc1 = 0.f;
    for (int j = s; j < t; j++) {
        int i = g_perm_n[j];
        int e = idx_e[i];
        acc0 += g_alpha[i * 2] * g_eout[(size_t)e * DM + d];
        acc1 += g_alpha[i * 2 + 1] * g_eout[(size_t)(NE + e) * DM + d];
    }
    float x2 = g_dinv[n] * 0.5f * (acc0 + acc1) + cb[d];
    float v = g_h1[(size_t)n * DM + d] + x2;
    v = g2[d] * (v - m2[d]) * rsqrtf(v2[d] + EPSV) + b2[d];
    g_hb[(size_t)n * DM + d] = v;
}

// ------------------------- launch -------------------------
extern "C" void kernel_launch(void* const* d_in, const int* in_sizes, int n_in,
                              void* d_out, int out_size) {
    const float* x    = (const float*)d_in[0];
    const int*   he   = (const int*)d_in[1];
    const int*   idx_n = he;
    const int*   idx_e = he + NI;
    const float* W1   = (const float*)d_in[2];
    const float* b1   = (const float*)d_in[3];
    const float* bn1g = (const float*)d_in[4];
    const float* bn1b = (const float*)d_in[5];
    const float* bn1m = (const float*)d_in[6];
    const float* bn1v = (const float*)d_in[7];
    const float* attW = (const float*)d_in[8];
    const float* att  = (const float*)d_in[9];
    const float* cb   = (const float*)d_in[10];
    const float* bn2g = (const float*)d_in[11];
    const float* bn2b = (const float*)d_in[12];
    const float* bn2m = (const float*)d_in[13];
    const float* bn2v = (const float*)d_in[14];
    const float* W2   = (const float*)d_in[15];
    const float* b2   = (const float*)d_in[16];
    const float* lng  = (const float*)d_in[17];
    const float* lnb  = (const float*)d_in[18];
    float* out = (float*)d_out;

    float *p_h1, *p_agg, *p_eout, *p_hb;
    int *p_cnt_n, *p_cnt_e, *p_off_n, *p_off_e, *p_cur_n, *p_cur_e;
    int *p_bsum_n, *p_bsum_e;
    cudaGetSymbolAddress((void**)&p_h1, g_h1);
    cudaGetSymbolAddress((void**)&p_agg, g_agg);
    cudaGetSymbolAddress((void**)&p_eout, g_eout);
    cudaGetSymbolAddress((void**)&p_hb, g_hb);
    cudaGetSymbolAddress((void**)&p_cnt_n, g_cnt_n);
    cudaGetSymbolAddress((void**)&p_cnt_e, g_cnt_e);
    cudaGetSymbolAddress((void**)&p_off_n, g_off_n);
    cudaGetSymbolAddress((void**)&p_off_e, g_off_e);
    cudaGetSymbolAddress((void**)&p_cur_n, g_cur_n);
    cudaGetSymbolAddress((void**)&p_cur_e, g_cur_e);
    cudaGetSymbolAddress((void**)&p_bsum_n, g_bsum_n);
    cudaGetSymbolAddress((void**)&p_bsum_e, g_bsum_e);

    // ---- CSR build ----
    k_zero_int<<<(NN + 255) / 256, 256>>>(p_cnt_n, NN);
    k_zero_int<<<(NE + 255) / 256, 256>>>(p_cnt_e, NE);
    k_hist<<<(NI + 255) / 256, 256>>>(idx_n, idx_e);
    k_scan_local<<<NN / 1024, 1024>>>(p_cnt_n, p_off_n, p_bsum_n, NN);
    k_scan_local<<<NE / 1024, 1024>>>(p_cnt_e, p_off_e, p_bsum_e, NE);
    k_scan_final<<<NN / 1024, 1024>>>(p_off_n, p_cur_n, p_bsum_n, NN / 1024, NN);
    k_scan_final<<<NE / 1024, 1024>>>(p_off_e, p_cur_e, p_bsum_e, NE / 1024, NE);
    k_scatter<<<(NI + 255) / 256, 256>>>(idx_n, idx_e);

    // ---- contracted attention weight vectors ----
    k_prepw<<<1, 512>>>(attW, att);

    // ---- GEMM 1: h1 = bn1(leaky(x @ W1^T + b1)) ----
    {
        dim3 grid(DM / 128, NN / 128, 1);
        k_gemm_mma<0><<<grid, 256>>>(x, W1, p_h1, DM, b1, bn1g, bn1b, bn1m, bn1v, 0, 0, 0);
    }

    // ---- node dots (sn, tn) + edge scores via scalar segment sum ----
    k_dot2<<<NN / 8, 256>>>();
    k_se<<<NE * 32 / 256, 256>>>(idx_n);

    // ---- segment softmax ----
    k_softmax<<<(NN + 255) / 256, 256>>>(idx_e);

    // ---- alpha-weighted aggregation ----
    k_agg<<<NE, 256>>>(idx_n);

    // ---- edge GEMM: eout[h] = agg[h] @ attW_h^T  (2 x [4096,256,256]) ----
    {
        dim3 grid(DM / 128, NE / 128, 2);
        k_gemm_mma<1><<<grid, 256>>>(p_agg, attW, p_eout, DM,
                                     nullptr, nullptr, nullptr, nullptr, nullptr,
                                     (size_t)NE * DM, (size_t)DM * DM, (size_t)NE * DM);
    }

    // ---- node aggregation + bn2 ----
    k_nodeout<<<NN, 256>>>(idx_e, cb, bn2g, bn2b, bn2m, bn2v);

    // ---- GEMM 3 fused with residual + LayerNorm: out = LN(x + leaky(hb @ W2^T + b2)) ----
    {
        dim3 grid(DM / 128, NN / 128, 1);
        k_gemm_mma<3><<<grid, 256>>>(p_hb, W2, out, DM, b2, lng, lnb, x, nullptr, 0, 0, 0);
    }
}

// round 8
// speedup vs baseline: 3.2766x; 1.0148x over previous
#include <cuda_runtime.h>
#include <math.h>

#define NN 32768
#define NE 4096
#define NI 131072
#define DM 256
#define EPSV 1e-5f
#define NEGS 0.2f

// ------------------------- device scratch -------------------------
__device__ float g_h1[NN * DM];          // post bn1 node features
__device__ float g_agg[2 * NE * DM];     // alpha-weighted h1 aggregate per edge, head-major
__device__ float g_eout[2 * NE * DM];    // edge_out, head-major [h][e][d]
__device__ float g_hb[NN * DM];          // bn2(h1 + x2)
__device__ float g_sn[NN * 2];
__device__ float g_tn[NN * 2];           // h1 . w_e  (per node, per head)
__device__ float g_se[NE * 2];
__device__ float g_alpha[NI * 2];
__device__ float g_wn[2 * DM];
__device__ float g_we[2 * DM];
__device__ float g_dinv[NN];
__device__ int g_cnt_n[NN], g_off_n[NN + 1], g_cur_n[NN];
__device__ int g_cnt_e[NE], g_off_e[NE + 1], g_cur_e[NE];
__device__ int g_perm_n[NI], g_perm_e[NI];
__device__ int g_bsum_n[32], g_bsum_e[4];

__device__ __forceinline__ float leaky(float v) { return v >= 0.f ? v : NEGS * v; }

__device__ __forceinline__ void cp16(void* dst, const void* src) {
    unsigned d = (unsigned)__cvta_generic_to_shared(dst);
    asm volatile("cp.async.cg.shared.global [%0], [%1], 16;" :: "r"(d), "l"(src) : "memory");
}

__device__ __forceinline__ void ldsm4(unsigned& r0, unsigned& r1, unsigned& r2, unsigned& r3,
                                      unsigned addr) {
    asm volatile("ldmatrix.sync.aligned.m8n8.x4.shared.b16 {%0,%1,%2,%3}, [%4];"
                 : "=r"(r0), "=r"(r1), "=r"(r2), "=r"(r3) : "r"(addr));
}

// ------------------------- CSR build -------------------------
__global__ void k_zero_int(int* a, int n) {
    int i = blockIdx.x * blockDim.x + threadIdx.x;
    if (i < n) a[i] = 0;
}

__global__ void k_hist(const int* __restrict__ idx_n, const int* __restrict__ idx_e) {
    int i = blockIdx.x * blockDim.x + threadIdx.x;
    if (i < NI) {
        atomicAdd(&g_cnt_n[idx_n[i]], 1);
        atomicAdd(&g_cnt_e[idx_e[i]], 1);
    }
}

__global__ void k_scan_local(const int* __restrict__ cnt, int* __restrict__ off,
                             int* __restrict__ bsum, int n) {
    __shared__ int ws[32];
    int t = threadIdx.x;
    int i = blockIdx.x * 1024 + t;
    int v = (i < n) ? cnt[i] : 0;
    int lane = t & 31, w = t >> 5;
    int s = v;
#pragma unroll
    for (int o = 1; o < 32; o <<= 1) {
        int u = __shfl_up_sync(0xffffffffu, s, o);
        if (lane >= o) s += u;
    }
    if (lane == 31) ws[w] = s;
    __syncthreads();
    if (w == 0) {
        int u = ws[lane];
#pragma unroll
        for (int o = 1; o < 32; o <<= 1) {
            int x2 = __shfl_up_sync(0xffffffffu, u, o);
            if (lane >= o) u += x2;
        }
        ws[lane] = u;
    }
    __syncthreads();
    int excl = s - v + (w > 0 ? ws[w - 1] : 0);
    if (i < n) off[i] = excl;
    if (t == 1023) bsum[blockIdx.x] = ws[31];
}

__global__ void k_scan_final(int* __restrict__ off, int* __restrict__ cur,
                             const int* __restrict__ bsum, int nb, int n) {
    __shared__ int pre;
    int b = blockIdx.x, t = threadIdx.x;
    if (t == 0) {
        int s = 0;
        for (int j = 0; j < b; j++) s += bsum[j];
        pre = s;
        if (b == nb - 1) off[n] = s + bsum[b];
    }
    __syncthreads();
    int i = b * 1024 + t;
    if (i < n) {
        int o = off[i] + pre;
        off[i] = o;
        cur[i] = o;
    }
}

__global__ void k_scatter(const int* __restrict__ idx_n, const int* __restrict__ idx_e) {
    int i = blockIdx.x * blockDim.x + threadIdx.x;
    if (i < NI) {
        int p = atomicAdd(&g_cur_n[idx_n[i]], 1);
        g_perm_n[p] = i;
        int q = atomicAdd(&g_cur_e[idx_e[i]], 1);
        g_perm_e[q] = i;
    }
}

// ------------------------- contracted attention vectors -------------------------
__global__ void k_prepw(const float* __restrict__ attW, const float* __restrict__ att) {
    int t = threadIdx.x;       // 0..511
    int h = t / DM, k = t % DM;
    float accn = 0.f, acce = 0.f;
    for (int d = 0; d < DM; d++) {
        float w = attW[(h * DM + d) * DM + k];
        accn += w * att[h * 2 * DM + d];
        acce += w * att[h * 2 * DM + DM + d];
    }
    g_wn[t] = accn;
    g_we[t] = acce;
}

// ------------------------- tf32 tensor-core GEMM, cp.async 2-stage + ldmatrix -----
// C[M,Nw] = A[M,256] @ W[Nw,256]^T ; block tile 128x128, 8 warps.
// MODE 0: bn1(leaky(acc+bias))
// MODE 1: raw
// MODE 3: y = leaky(acc+bias) + xres(flat) ; LayerNorm over 64-col groups ; write out(flat)
//         (param aliases: bg=ln_g, bb=ln_b, bm=xres)
// blockIdx.z head support via zsA/zsW/zsC element strides.
template <int MODE>
__global__ void __launch_bounds__(256) k_gemm_mma(
    const float* __restrict__ A, const float* __restrict__ W,
    float* __restrict__ C, int Nw,
    const float* __restrict__ bias,
    const float* __restrict__ bg, const float* __restrict__ bb,
    const float* __restrict__ bm, const float* __restrict__ bv,
    size_t zsA, size_t zsW, size_t zsC) {
    // k-chunk 16, rows padded to 20 floats (80B: 16B-aligned, conflict-free)
    __shared__ alignas(16) float As[2][128][20];
    __shared__ alignas(16) float Ws[2][128][20];
    A += blockIdx.z * zsA;
    W += blockIdx.z * zsW;
    C += blockIdx.z * zsC;
    int tid = threadIdx.x;
    int lane = tid & 31;
    int warp = tid >> 5;
    int wm = warp >> 2;           // 0..1
    int wn = warp & 3;            // 0..3
    int m0 = blockIdx.y * 128;
    int n0 = blockIdx.x * 128;
    int gid = lane >> 2;          // 0..7
    int tig = lane & 3;           // 0..3

    float acc[4][4][4];
#pragma unroll
    for (int mt = 0; mt < 4; mt++)
#pragma unroll
        for (int nt = 0; nt < 4; nt++)
#pragma unroll
            for (int c = 0; c < 4; c++) acc[mt][nt][c] = 0.f;

    // ldmatrix per-lane base addresses (stage 0, kb 0)
    // A mt-tile: matrix i: rows {0-7|8-15 by i&1}, col block {0|4 by i>>1}
    unsigned aoff[4], boff[2];
    {
        unsigned baseA = (unsigned)__cvta_generic_to_shared(&As[0][0][0]);
        unsigned baseW = (unsigned)__cvta_generic_to_shared(&Ws[0][0][0]);
        int i = lane >> 3, rr = lane & 7;
#pragma unroll
        for (int mt = 0; mt < 4; mt++) {
            int row = wm * 64 + mt * 16 + (i & 1) * 8 + rr;
            int col = (i >> 1) * 4;
            aoff[mt] = baseA + (row * 20 + col) * 4;
        }
        // B nt-pair j: matrix i: nt = j*2 + (i>>1), col block {0|4 by i&1}
#pragma unroll
        for (int j = 0; j < 2; j++) {
            int row = wn * 32 + (j * 2 + (i >> 1)) * 8 + rr;
            int col = (i & 1) * 4;
            boff[j] = baseW + (row * 20 + col) * 4;
        }
    }
    const unsigned stgA = 128 * 20 * 4;   // stage stride bytes

    // per-thread cp.async assignment: 128 rows x 4 chunks(16B) per matrix
    int r0 = tid >> 2;               // 0..63
    int c0 = (tid & 3) << 2;         // 0,4,8,12

    auto issue_tile = [&](int kc, int st) {
        cp16(&As[st][r0][c0], &A[(size_t)(m0 + r0) * 256 + kc + c0]);
        cp16(&As[st][r0 + 64][c0], &A[(size_t)(m0 + r0 + 64) * 256 + kc + c0]);
        cp16(&Ws[st][r0][c0], &W[(size_t)(n0 + r0) * 256 + kc + c0]);
        cp16(&Ws[st][r0 + 64][c0], &W[(size_t)(n0 + r0 + 64) * 256 + kc + c0]);
        asm volatile("cp.async.commit_group;" ::: "memory");
    };

    issue_tile(0, 0);
#pragma unroll 4
    for (int it = 0; it < 16; it++) {
        int st = it & 1;
        if (it < 15) {
            issue_tile((it + 1) * 16, st ^ 1);
            asm volatile("cp.async.wait_group 1;" ::: "memory");
        } else {
            asm volatile("cp.async.wait_group 0;" ::: "memory");
        }
        __syncthreads();
#pragma unroll
        for (int kk = 0; kk < 2; kk++) {
            unsigned koff = st * stgA + kk * 32;   // kb = kk*8 floats = 32 bytes
            unsigned af[4][4];
#pragma unroll
            for (int mt = 0; mt < 4; mt++)
                ldsm4(af[mt][0], af[mt][1], af[mt][2], af[mt][3], aoff[mt] + koff);
            unsigned bf[4][2];
#pragma unroll
            for (int j = 0; j < 2; j++)
                ldsm4(bf[j * 2][0], bf[j * 2][1], bf[j * 2 + 1][0], bf[j * 2 + 1][1],
                      boff[j] + koff);
#pragma unroll
            for (int mt = 0; mt < 4; mt++)
#pragma unroll
                for (int nt = 0; nt < 4; nt++) {
                    asm volatile(
                        "mma.sync.aligned.m16n8k8.row.col.f32.tf32.tf32.f32 "
                        "{%0,%1,%2,%3}, {%4,%5,%6,%7}, {%8,%9}, {%0,%1,%2,%3};"
                        : "+f"(acc[mt][nt][0]), "+f"(acc[mt][nt][1]),
                          "+f"(acc[mt][nt][2]), "+f"(acc[mt][nt][3])
                        : "r"(af[mt][0]), "r"(af[mt][1]), "r"(af[mt][2]), "r"(af[mt][3]),
                          "r"(bf[nt][0]), "r"(bf[nt][1]));
                }
        }
        __syncthreads();
    }

    if (MODE == 3) {
        // y = leaky(acc + bias) + x(flat) ; LN over 64-column groups (2 per block).
        float* sred = &As[0][0][0];     // [128 rows][2 grp][2 {s,ss}]
        for (int i = tid; i < 128 * 2 * 2; i += 256) sred[i] = 0.f;
        __syncthreads();
        int grp = wn >> 1;
        const float* xres = bm;
#pragma unroll
        for (int mt = 0; mt < 4; mt++) {
#pragma unroll
            for (int half = 0; half < 2; half++) {
                int rloc = wm * 64 + mt * 16 + gid + half * 8;
                int m = m0 + rloc;
                float s = 0.f, ss = 0.f;
#pragma unroll
                for (int nt = 0; nt < 4; nt++) {
                    int col = n0 + wn * 32 + nt * 8 + tig * 2;
                    size_t fi = (size_t)m * 256 + col;
                    float2 xv = *(const float2*)&xres[fi];
                    float y0 = leaky(acc[mt][nt][half * 2 + 0] + bias[col]) + xv.x;
                    float y1 = leaky(acc[mt][nt][half * 2 + 1] + bias[col + 1]) + xv.y;
                    acc[mt][nt][half * 2 + 0] = y0;
                    acc[mt][nt][half * 2 + 1] = y1;
                    s += y0 + y1;
                    ss += y0 * y0 + y1 * y1;
                }
                s += __shfl_xor_sync(0xffffffffu, s, 1);
                ss += __shfl_xor_sync(0xffffffffu, ss, 1);
                s += __shfl_xor_sync(0xffffffffu, s, 2);
                ss += __shfl_xor_sync(0xffffffffu, ss, 2);
                if (tig == 0) {
                    atomicAdd(&sred[(rloc * 2 + grp) * 2 + 0], s);
                    atomicAdd(&sred[(rloc * 2 + grp) * 2 + 1], ss);
                }
            }
        }
        __syncthreads();
#pragma unroll
        for (int mt = 0; mt < 4; mt++) {
#pragma unroll
            for (int half = 0; half < 2; half++) {
                int rloc = wm * 64 + mt * 16 + gid + half * 8;
                int m = m0 + rloc;
                float s = sred[(rloc * 2 + grp) * 2 + 0];
                float ss = sred[(rloc * 2 + grp) * 2 + 1];
                float mu = s * (1.0f / 64.0f);
                float var = ss * (1.0f / 64.0f) - mu * mu;
                float rs = rsqrtf(var + EPSV);
#pragma unroll
                for (int nt = 0; nt < 4; nt++) {
                    int col = n0 + wn * 32 + nt * 8 + tig * 2;
                    int c = col & 63;
                    float y0 = acc[mt][nt][half * 2 + 0];
                    float y1 = acc[mt][nt][half * 2 + 1];
                    float2 o = make_float2(bg[c] * (y0 - mu) * rs + bb[c],
                                           bg[c + 1] * (y1 - mu) * rs + bb[c + 1]);
                    *(float2*)&C[(size_t)m * 256 + col] = o;
                }
            }
        }
        return;
    }

    // epilogue (MODE 0/1)
#pragma unroll
    for (int mt = 0; mt < 4; mt++) {
        int row0 = m0 + wm * 64 + mt * 16 + gid;
#pragma unroll
        for (int nt = 0; nt < 4; nt++) {
            int col = n0 + wn * 32 + nt * 8 + tig * 2;
#pragma unroll
            for (int half = 0; half < 2; half++) {
                int row = row0 + half * 8;
                float v0 = acc[mt][nt][half * 2 + 0];
                float v1 = acc[mt][nt][half * 2 + 1];
                if (MODE == 0) {
                    v0 = leaky(v0 + bias[col]);
                    v1 = leaky(v1 + bias[col + 1]);
                    v0 = bg[col] * (v0 - bm[col]) * rsqrtf(bv[col] + EPSV) + bb[col];
                    v1 = bg[col + 1] * (v1 - bm[col + 1]) * rsqrtf(bv[col + 1] + EPSV) + bb[col + 1];
                }
                float2 o = make_float2(v0, v1);
                *(float2*)&C[(size_t)row * Nw + col] = o;
            }
        }
    }
}

// ------------------------- per-node dual dots: sn = h1.wn, tn = h1.we ----------
__global__ void __launch_bounds__(256) k_dot2() {
    __shared__ float w[4][DM];
    int tid = threadIdx.x;
    for (int i = tid; i < 4 * DM; i += 256) {
        int a = i >> 8, k = i & 255;
        w[a][k] = (a < 2) ? g_wn[a * DM + k] : g_we[(a - 2) * DM + k];
    }
    __syncthreads();
    int warp = tid >> 5, lane = tid & 31;
    int n = blockIdx.x * 8 + warp;
    int kb = lane * 8;
    float4 v0 = *(const float4*)&g_h1[(size_t)n * DM + kb];
    float4 v1 = *(const float4*)&g_h1[(size_t)n * DM + kb + 4];
    float acc[4];
#pragma unroll
    for (int a = 0; a < 4; a++) {
        const float* wa = &w[a][kb];
        acc[a] = v0.x * wa[0] + v0.y * wa[1] + v0.z * wa[2] + v0.w * wa[3]
               + v1.x * wa[4] + v1.y * wa[5] + v1.z * wa[6] + v1.w * wa[7];
#pragma unroll
        for (int o = 16; o; o >>= 1) acc[a] += __shfl_xor_sync(0xffffffffu, acc[a], o);
    }
    if (lane == 0) {
        g_sn[n * 2] = acc[0];
        g_sn[n * 2 + 1] = acc[1];
        g_tn[n * 2] = acc[2];
        g_tn[n * 2 + 1] = acc[3];
    }
}

// ------------------------- se[e,h] = sum_i tn[n_i,h]  (scalar segment sum) ------
__global__ void k_se(const int* __restrict__ idx_n) {
    int gw = (blockIdx.x * blockDim.x + threadIdx.x) >> 5;
    int lane = threadIdx.x & 31;
    if (gw >= NE) return;
    int s = g_off_e[gw], t = g_off_e[gw + 1];
    float a0 = 0.f, a1 = 0.f;
    for (int j = s + lane; j < t; j += 32) {
        int n = idx_n[g_perm_e[j]];
        a0 += g_tn[n * 2];
        a1 += g_tn[n * 2 + 1];
    }
#pragma unroll
    for (int o = 16; o; o >>= 1) {
        a0 += __shfl_xor_sync(0xffffffffu, a0, o);
        a1 += __shfl_xor_sync(0xffffffffu, a1, o);
    }
    if (lane == 0) {
        g_se[gw * 2] = a0;
        g_se[gw * 2 + 1] = a1;
    }
}

// ------------------------- per-node segment softmax -------------------------
__global__ void k_softmax(const int* __restrict__ idx_e) {
    int n = blockIdx.x * blockDim.x + threadIdx.x;
    if (n >= NN) return;
    int s = g_off_n[n], t = g_off_n[n + 1];
    int deg = t - s;
    g_dinv[n] = deg > 0 ? 1.0f / (float)deg : 0.0f;
    if (deg == 0) return;
    float sn0 = g_sn[n * 2], sn1 = g_sn[n * 2 + 1];
    float m0 = -3.402823e38f, m1 = -3.402823e38f;
    for (int j = s; j < t; j++) {
        int i = g_perm_n[j];
        int e = idx_e[i];
        float a0 = leaky(sn0 + g_se[e * 2]);
        float a1 = leaky(sn1 + g_se[e * 2 + 1]);
        m0 = fmaxf(m0, a0);
        m1 = fmaxf(m1, a1);
    }
    float d0 = 0.f, d1 = 0.f;
    for (int j = s; j < t; j++) {
        int i = g_perm_n[j];
        int e = idx_e[i];
        float e0 = expf(leaky(sn0 + g_se[e * 2]) - m0);
        float e1 = expf(leaky(sn1 + g_se[e * 2 + 1]) - m1);
        d0 += e0;
        d1 += e1;
        g_alpha[i * 2] = e0;
        g_alpha[i * 2 + 1] = e1;
    }
    float r0 = 1.0f / (d0 + 1e-16f);
    float r1 = 1.0f / (d1 + 1e-16f);
    for (int j = s; j < t; j++) {
        int i = g_perm_n[j];
        g_alpha[i * 2] *= r0;
        g_alpha[i * 2 + 1] *= r1;
    }
}

// ------------------------- alpha-weighted edge aggregation (both heads, one pass) ----
__global__ void __launch_bounds__(256) k_agg(const int* __restrict__ idx_n) {
    int e = blockIdx.x;
    int d = threadIdx.x;   // 256
    int s = g_off_e[e], t = g_off_e[e + 1];
    float binv = (t > s) ? 1.0f / (float)(t - s) : 0.0f;
    float a0 = 0.f, a1 = 0.f;
    for (int j = s; j < t; j++) {
        int i = g_perm_e[j];
        int n = idx_n[i];
        float v = g_h1[(size_t)n * DM + d];
        a0 += g_alpha[i * 2] * v;
        a1 += g_alpha[i * 2 + 1] * v;
    }
    g_agg[(size_t)e * DM + d] = binv * a0;
    g_agg[(size_t)(NE + e) * DM + d] = binv * a1;
}

// ------------------------- node_out + mean heads + cb + bn2 -------------------------
__global__ void __launch_bounds__(256) k_nodeout(
    const int* __restrict__ idx_e, const float* __restrict__ cb,
    const float* __restrict__ g2, const float* __restrict__ b2,
    const float* __restrict__ m2, const float* __restrict__ v2) {
    int n = blockIdx.x;
    int d = threadIdx.x;   // 256
    int s = g_off_n[n], t = g_off_n[n + 1];
    float acc0 = 0.f, acc1 = 0.f;
    for (int j = s; j < t; j++) {
        int i = g_perm_n[j];
        int e = idx_e[i];
        acc0 += g_alpha[i * 2] * g_eout[(size_t)e * DM + d];
        acc1 += g_alpha[i * 2 + 1] * g_eout[(size_t)(NE + e) * DM + d];
    }
    float x2 = g_dinv[n] * 0.5f * (acc0 + acc1) + cb[d];
    float v = g_h1[(size_t)n * DM + d] + x2;
    v = g2[d] * (v - m2[d]) * rsqrtf(v2[d] + EPSV) + b2[d];
    g_hb[(size_t)n * DM + d] = v;
}

// ------------------------- launch -------------------------
extern "C" void kernel_launch(void* const* d_in, const int* in_sizes, int n_in,
                              void* d_out, int out_size) {
    const float* x    = (const float*)d_in[0];
    const int*   he   = (const int*)d_in[1];
    const int*   idx_n = he;
    const int*   idx_e = he + NI;
    const float* W1   = (const float*)d_in[2];
    const float* b1   = (const float*)d_in[3];
    const float* bn1g = (const float*)d_in[4];
    const float* bn1b = (const float*)d_in[5];
    const float* bn1m = (const float*)d_in[6];
    const float* bn1v = (const float*)d_in[7];
    const float* attW = (const float*)d_in[8];
    const float* att  = (const float*)d_in[9];
    const float* cb   = (const float*)d_in[10];
    const float* bn2g = (const float*)d_in[11];
    const float* bn2b = (const float*)d_in[12];
    const float* bn2m = (const float*)d_in[13];
    const float* bn2v = (const float*)d_in[14];
    const float* W2   = (const float*)d_in[15];
    const float* b2   = (const float*)d_in[16];
    const float* lng  = (const float*)d_in[17];
    const float* lnb  = (const float*)d_in[18];
    float* out = (float*)d_out;

    float *p_h1, *p_agg, *p_eout, *p_hb;
    int *p_cnt_n, *p_cnt_e, *p_off_n, *p_off_e, *p_cur_n, *p_cur_e;
    int *p_bsum_n, *p_bsum_e;
    cudaGetSymbolAddress((void**)&p_h1, g_h1);
    cudaGetSymbolAddress((void**)&p_agg, g_agg);
    cudaGetSymbolAddress((void**)&p_eout, g_eout);
    cudaGetSymbolAddress((void**)&p_hb, g_hb);
    cudaGetSymbolAddress((void**)&p_cnt_n, g_cnt_n);
    cudaGetSymbolAddress((void**)&p_cnt_e, g_cnt_e);
    cudaGetSymbolAddress((void**)&p_off_n, g_off_n);
    cudaGetSymbolAddress((void**)&p_off_e, g_off_e);
    cudaGetSymbolAddress((void**)&p_cur_n, g_cur_n);
    cudaGetSymbolAddress((void**)&p_cur_e, g_cur_e);
    cudaGetSymbolAddress((void**)&p_bsum_n, g_bsum_n);
    cudaGetSymbolAddress((void**)&p_bsum_e, g_bsum_e);

    // ---- CSR build ----
    k_zero_int<<<(NN + 255) / 256, 256>>>(p_cnt_n, NN);
    k_zero_int<<<(NE + 255) / 256, 256>>>(p_cnt_e, NE);
    k_hist<<<(NI + 255) / 256, 256>>>(idx_n, idx_e);
    k_scan_local<<<NN / 1024, 1024>>>(p_cnt_n, p_off_n, p_bsum_n, NN);
    k_scan_local<<<NE / 1024, 1024>>>(p_cnt_e, p_off_e, p_bsum_e, NE);
    k_scan_final<<<NN / 1024, 1024>>>(p_off_n, p_cur_n, p_bsum_n, NN / 1024, NN);
    k_scan_final<<<NE / 1024, 1024>>>(p_off_e, p_cur_e, p_bsum_e, NE / 1024, NE);
    k_scatter<<<(NI + 255) / 256, 256>>>(idx_n, idx_e);

    // ---- contracted attention weight vectors ----
    k_prepw<<<1, 512>>>(attW, att);

    // ---- GEMM 1: h1 = bn1(leaky(x @ W1^T + b1)) ----
    {
        dim3 grid(DM / 128, NN / 128, 1);
        k_gemm_mma<0><<<grid, 256>>>(x, W1, p_h1, DM, b1, bn1g, bn1b, bn1m, bn1v, 0, 0, 0);
    }

    // ---- node dots (sn, tn) + edge scores via scalar segment sum ----
    k_dot2<<<NN / 8, 256>>>();
    k_se<<<NE * 32 / 256, 256>>>(idx_n);

    // ---- segment softmax ----
    k_softmax<<<(NN + 255) / 256, 256>>>(idx_e);

    // ---- alpha-weighted aggregation ----
    k_agg<<<NE, 256>>>(idx_n);

    // ---- edge GEMM: eout[h] = agg[h] @ attW_h^T  (2 x [4096,256,256]) ----
    {
        dim3 grid(DM / 128, NE / 128, 2);
        k_gemm_mma<1><<<grid, 256>>>(p_agg, attW, p_eout, DM,
                                     nullptr, nullptr, nullptr, nullptr, nullptr,
                                     (size_t)NE * DM, (size_t)DM * DM, (size_t)NE * DM);
    }

    // ---- node aggregation + bn2 ----
    k_nodeout<<<NN, 256>>>(idx_e, cb, bn2g, bn2b, bn2m, bn2v);

    // ---- GEMM 3 fused with residual + LayerNorm: out = LN(x + leaky(hb @ W2^T + b2)) ----
    {
        dim3 grid(DM / 128, NN / 128, 1);
        k_gemm_mma<3><<<grid, 256>>>(p_hb, W2, out, DM, b2, lng, lnb, x, nullptr, 0, 0, 0);
    }
}

// round 10
// speedup vs baseline: 3.7847x; 1.1551x over previous
#include <cuda_runtime.h>
#include <cuda_fp16.h>
#include <math.h>
#include <stdint.h>

#define NN 32768
#define NE 4096
#define NI 131072
#define DM 256
#define EPSV 1e-5f
#define NEGS 0.2f

// ------------------------- device scratch -------------------------
__device__ float g_h1[NN * DM];          // post bn1 node features (f32)
__device__ __half g_x16[NN * DM];        // x in fp16 (GEMM1 A)
__device__ __half g_W1h[DM * DM];
__device__ __half g_W2h[DM * DM];
__device__ __half g_attWh[2 * DM * DM];
__device__ __half g_agg16[2 * NE * DM];  // alpha-weighted aggregate (fp16, edge GEMM A)
__device__ float g_eout[2 * NE * DM];    // edge_out (f32)
__device__ __half g_hb16[NN * DM];       // bn2(h1+x2) in fp16 (GEMM3 A)
__device__ float g_sn[NN * 2];
__device__ float g_tn[NN * 2];
__device__ float g_se[NE * 2];
__device__ float g_alpha[NI * 2];
__device__ float g_wn[2 * DM];
__device__ float g_we[2 * DM];
__device__ float g_dinv[NN];
__device__ int g_cnt_n[NN], g_off_n[NN + 1], g_cur_n[NN];
__device__ int g_cnt_e[NE], g_off_e[NE + 1], g_cur_e[NE];
__device__ int g_perm_n[NI], g_perm_e[NI];
__device__ int g_bsum_n[32], g_bsum_e[4];

__device__ __forceinline__ float leaky(float v) { return v >= 0.f ? v : NEGS * v; }

__device__ __forceinline__ void cp16(void* dst, const void* src) {
    unsigned d = (unsigned)__cvta_generic_to_shared(dst);
    asm volatile("cp.async.cg.shared.global [%0], [%1], 16;" :: "r"(d), "l"(src) : "memory");
}

__device__ __forceinline__ void ldsm4(unsigned& r0, unsigned& r1, unsigned& r2, unsigned& r3,
                                      unsigned addr) {
    asm volatile("ldmatrix.sync.aligned.m8n8.x4.shared.b16 {%0,%1,%2,%3}, [%4];"
                 : "=r"(r0), "=r"(r1), "=r"(r2), "=r"(r3) : "r"(addr));
}

// ------------------------- fp32 -> fp16 conversion -------------------------
__global__ void k_cvt(const float* __restrict__ src, __half* __restrict__ dst, int n) {
    int i = (blockIdx.x * blockDim.x + threadIdx.x) * 4;
    if (i < n) {
        float4 v = *(const float4*)&src[i];
        __half2 a = __floats2half2_rn(v.x, v.y);
        __half2 b = __floats2half2_rn(v.z, v.w);
        uint2 o = make_uint2(*(unsigned*)&a, *(unsigned*)&b);
        *(uint2*)&dst[i] = o;
    }
}

// ------------------------- CSR build -------------------------
__global__ void k_zero_int(int* a, int n) {
    int i = blockIdx.x * blockDim.x + threadIdx.x;
    if (i < n) a[i] = 0;
}

__global__ void k_hist(const int* __restrict__ idx_n, const int* __restrict__ idx_e) {
    int i = blockIdx.x * blockDim.x + threadIdx.x;
    if (i < NI) {
        atomicAdd(&g_cnt_n[idx_n[i]], 1);
        atomicAdd(&g_cnt_e[idx_e[i]], 1);
    }
}

__global__ void k_scan_local(const int* __restrict__ cnt, int* __restrict__ off,
                             int* __restrict__ bsum, int n) {
    __shared__ int ws[32];
    int t = threadIdx.x;
    int i = blockIdx.x * 1024 + t;
    int v = (i < n) ? cnt[i] : 0;
    int lane = t & 31, w = t >> 5;
    int s = v;
#pragma unroll
    for (int o = 1; o < 32; o <<= 1) {
        int u = __shfl_up_sync(0xffffffffu, s, o);
        if (lane >= o) s += u;
    }
    if (lane == 31) ws[w] = s;
    __syncthreads();
    if (w == 0) {
        int u = ws[lane];
#pragma unroll
        for (int o = 1; o < 32; o <<= 1) {
            int x2 = __shfl_up_sync(0xffffffffu, u, o);
            if (lane >= o) u += x2;
        }
        ws[lane] = u;
    }
    __syncthreads();
    int excl = s - v + (w > 0 ? ws[w - 1] : 0);
    if (i < n) off[i] = excl;
    if (t == 1023) bsum[blockIdx.x] = ws[31];
}

__global__ void k_scan_final(int* __restrict__ off, int* __restrict__ cur,
                             const int* __restrict__ bsum, int nb, int n) {
    __shared__ int pre;
    int b = blockIdx.x, t = threadIdx.x;
    if (t == 0) {
        int s = 0;
        for (int j = 0; j < b; j++) s += bsum[j];
        pre = s;
        if (b == nb - 1) off[n] = s + bsum[b];
    }
    __syncthreads();
    int i = b * 1024 + t;
    if (i < n) {
        int o = off[i] + pre;
        off[i] = o;
        cur[i] = o;
    }
}

__global__ void k_scatter(const int* __restrict__ idx_n, const int* __restrict__ idx_e) {
    int i = blockIdx.x * blockDim.x + threadIdx.x;
    if (i < NI) {
        int p = atomicAdd(&g_cur_n[idx_n[i]], 1);
        g_perm_n[p] = i;
        int q = atomicAdd(&g_cur_e[idx_e[i]], 1);
        g_perm_e[q] = i;
    }
}

// ------------------------- contracted attention vectors -------------------------
__global__ void k_prepw(const float* __restrict__ attW, const float* __restrict__ att) {
    int t = threadIdx.x;       // 0..511
    int h = t / DM, k = t % DM;
    float accn = 0.f, acce = 0.f;
    for (int d = 0; d < DM; d++) {
        float w = attW[(h * DM + d) * DM + k];
        accn += w * att[h * 2 * DM + d];
        acce += w * att[h * 2 * DM + DM + d];
    }
    g_wn[t] = accn;
    g_we[t] = acce;
}

// ------------------------- fp16 tensor-core GEMM, cp.async 2-stage + ldmatrix ----
// C[M,Nw] = A[M,256] @ W[Nw,256]^T ; A,W fp16 ; block tile 128x128, 8 warps,
// warp tile 64x32, mma.m16n8k16.f16 with f32 accumulate.
// MODE 0: bn1(leaky(acc+bias))
// MODE 1: raw
// MODE 3: y = leaky(acc+bias) + xres(flat) ; LayerNorm over 64-col groups ; write out(flat)
//         (param aliases: bg=ln_g, bb=ln_b, bm=xres)
template <int MODE>
__global__ void __launch_bounds__(256) k_gemm_mma(
    const __half* __restrict__ A, const __half* __restrict__ W,
    float* __restrict__ C, int Nw,
    const float* __restrict__ bias,
    const float* __restrict__ bg, const float* __restrict__ bb,
    const float* __restrict__ bm, const float* __restrict__ bv,
    size_t zsA, size_t zsW, size_t zsC) {
    // k-chunk 32 halves (64B/row), rows padded to 40 halves (80B: 16B-aligned,
    // conflict-free: 80r mod 128 distinct over 8-row ldmatrix groups)
    __shared__ alignas(16) __half As[2][128][40];
    __shared__ alignas(16) __half Ws[2][128][40];
    A += blockIdx.z * zsA;
    W += blockIdx.z * zsW;
    C += blockIdx.z * zsC;
    int tid = threadIdx.x;
    int lane = tid & 31;
    int warp = tid >> 5;
    int wm = warp >> 2;           // 0..1
    int wn = warp & 3;            // 0..3
    int m0 = blockIdx.y * 128;
    int n0 = blockIdx.x * 128;
    int gid = lane >> 2;          // 0..7
    int tig = lane & 3;           // 0..3

    float acc[4][4][4];
#pragma unroll
    for (int mt = 0; mt < 4; mt++)
#pragma unroll
        for (int nt = 0; nt < 4; nt++)
#pragma unroll
            for (int c = 0; c < 4; c++) acc[mt][nt][c] = 0.f;

    // ldmatrix per-lane base addresses (stage 0, k-step 0); col units = halves
    unsigned aoff[4], boff[2];
    {
        unsigned baseA = (unsigned)__cvta_generic_to_shared(&As[0][0][0]);
        unsigned baseW = (unsigned)__cvta_generic_to_shared(&Ws[0][0][0]);
        int i = lane >> 3, rr = lane & 7;
#pragma unroll
        for (int mt = 0; mt < 4; mt++) {
            int row = wm * 64 + mt * 16 + (i & 1) * 8 + rr;
            int col = (i >> 1) * 8;             // k 0-7 | 8-15 (16B blocks)
            aoff[mt] = baseA + (row * 40 + col) * 2;
        }
#pragma unroll
        for (int j = 0; j < 2; j++) {
            int row = wn * 32 + (j * 2 + (i >> 1)) * 8 + rr;
            int col = (i & 1) * 8;
            boff[j] = baseW + (row * 40 + col) * 2;
        }
    }
    const unsigned stgA = 128 * 40 * 2;   // stage stride bytes

    // cp.async: 128 rows x 4 chunks(16B = 8 halves) per matrix
    int r0 = tid >> 2;               // 0..63
    int c0 = (tid & 3) << 3;         // 0,8,16,24 halves

    auto issue_tile = [&](int kc, int st) {
        cp16(&As[st][r0][c0], A + (size_t)(m0 + r0) * 256 + kc + c0);
        cp16(&As[st][r0 + 64][c0], A + (size_t)(m0 + r0 + 64) * 256 + kc + c0);
        cp16(&Ws[st][r0][c0], W + (size_t)(n0 + r0) * 256 + kc + c0);
        cp16(&Ws[st][r0 + 64][c0], W + (size_t)(n0 + r0 + 64) * 256 + kc + c0);
        asm volatile("cp.async.commit_group;" ::: "memory");
    };

    issue_tile(0, 0);
#pragma unroll
    for (int it = 0; it < 8; it++) {
        int st = it & 1;
        if (it < 7) {
            issue_tile((it + 1) * 32, st ^ 1);
            asm volatile("cp.async.wait_group 1;" ::: "memory");
        } else {
            asm volatile("cp.async.wait_group 0;" ::: "memory");
        }
        __syncthreads();
#pragma unroll
        for (int kk = 0; kk < 2; kk++) {
            unsigned koff = st * stgA + kk * 32;   // 16 halves = 32 bytes
            unsigned af[4][4];
#pragma unroll
            for (int mt = 0; mt < 4; mt++)
                ldsm4(af[mt][0], af[mt][1], af[mt][2], af[mt][3], aoff[mt] + koff);
            unsigned bf[4][2];
#pragma unroll
            for (int j = 0; j < 2; j++)
                ldsm4(bf[j * 2][0], bf[j * 2][1], bf[j * 2 + 1][0], bf[j * 2 + 1][1],
                      boff[j] + koff);
#pragma unroll
            for (int mt = 0; mt < 4; mt++)
#pragma unroll
                for (int nt = 0; nt < 4; nt++) {
                    asm volatile(
                        "mma.sync.aligned.m16n8k16.row.col.f32.f16.f16.f32 "
                        "{%0,%1,%2,%3}, {%4,%5,%6,%7}, {%8,%9}, {%0,%1,%2,%3};"
                        : "+f"(acc[mt][nt][0]), "+f"(acc[mt][nt][1]),
                          "+f"(acc[mt][nt][2]), "+f"(acc[mt][nt][3])
                        : "r"(af[mt][0]), "r"(af[mt][1]), "r"(af[mt][2]), "r"(af[mt][3]),
                          "r"(bf[nt][0]), "r"(bf[nt][1]));
                }
        }
        __syncthreads();
    }

    if (MODE == 3) {
        // y = leaky(acc + bias) + x(flat) ; LN over 64-column groups (2 per block).
        float* sred = (float*)&As[0][0][0];   // [128 rows][2 grp][2 {s,ss}]
        for (int i = tid; i < 128 * 2 * 2; i += 256) sred[i] = 0.f;
        __syncthreads();
        int grp = wn >> 1;
        const float* xres = bm;
#pragma unroll
        for (int mt = 0; mt < 4; mt++) {
#pragma unroll
            for (int half = 0; half < 2; half++) {
                int rloc = wm * 64 + mt * 16 + gid + half * 8;
                int m = m0 + rloc;
                float s = 0.f, ss = 0.f;
#pragma unroll
                for (int nt = 0; nt < 4; nt++) {
                    int col = n0 + wn * 32 + nt * 8 + tig * 2;
                    size_t fi = (size_t)m * 256 + col;
                    float2 xv = *(const float2*)&xres[fi];
                    float y0 = leaky(acc[mt][nt][half * 2 + 0] + bias[col]) + xv.x;
                    float y1 = leaky(acc[mt][nt][half * 2 + 1] + bias[col + 1]) + xv.y;
                    acc[mt][nt][half * 2 + 0] = y0;
                    acc[mt][nt][half * 2 + 1] = y1;
                    s += y0 + y1;
                    ss += y0 * y0 + y1 * y1;
                }
                s += __shfl_xor_sync(0xffffffffu, s, 1);
                ss += __shfl_xor_sync(0xffffffffu, ss, 1);
                s += __shfl_xor_sync(0xffffffffu, s, 2);
                ss += __shfl_xor_sync(0xffffffffu, ss, 2);
                if (tig == 0) {
                    atomicAdd(&sred[(rloc * 2 + grp) * 2 + 0], s);
                    atomicAdd(&sred[(rloc * 2 + grp) * 2 + 1], ss);
                }
            }
        }
        __syncthreads();
#pragma unroll
        for (int mt = 0; mt < 4; mt++) {
#pragma unroll
            for (int half = 0; half < 2; half++) {
                int rloc = wm * 64 + mt * 16 + gid + half * 8;
                int m = m0 + rloc;
                float s = sred[(rloc * 2 + grp) * 2 + 0];
                float ss = sred[(rloc * 2 + grp) * 2 + 1];
                float mu = s * (1.0f / 64.0f);
                float var = ss * (1.0f / 64.0f) - mu * mu;
                float rs = rsqrtf(var + EPSV);
#pragma unroll
                for (int nt = 0; nt < 4; nt++) {
                    int col = n0 + wn * 32 + nt * 8 + tig * 2;
                    int c = col & 63;
                    float y0 = acc[mt][nt][half * 2 + 0];
                    float y1 = acc[mt][nt][half * 2 + 1];
                    float2 o = make_float2(bg[c] * (y0 - mu) * rs + bb[c],
                                           bg[c + 1] * (y1 - mu) * rs + bb[c + 1]);
                    *(float2*)&C[(size_t)m * 256 + col] = o;
                }
            }
        }
        return;
    }

    // epilogue (MODE 0/1)
#pragma unroll
    for (int mt = 0; mt < 4; mt++) {
        int row0 = m0 + wm * 64 + mt * 16 + gid;
#pragma unroll
        for (int nt = 0; nt < 4; nt++) {
            int col = n0 + wn * 32 + nt * 8 + tig * 2;
#pragma unroll
            for (int half = 0; half < 2; half++) {
                int row = row0 + half * 8;
                float v0 = acc[mt][nt][half * 2 + 0];
                float v1 = acc[mt][nt][half * 2 + 1];
                if (MODE == 0) {
                    v0 = leaky(v0 + bias[col]);
                    v1 = leaky(v1 + bias[col + 1]);
                    v0 = bg[col] * (v0 - bm[col]) * rsqrtf(bv[col] + EPSV) + bb[col];
                    v1 = bg[col + 1] * (v1 - bm[col + 1]) * rsqrtf(bv[col + 1] + EPSV) + bb[col + 1];
                }
                float2 o = make_float2(v0, v1);
                *(float2*)&C[(size_t)row * Nw + col] = o;
            }
        }
    }
}

// ------------------------- per-node dual dots: sn = h1.wn, tn = h1.we ----------
__global__ void __launch_bounds__(256) k_dot2() {
    __shared__ float w[4][DM];
    int tid = threadIdx.x;
    for (int i = tid; i < 4 * DM; i += 256) {
        int a = i >> 8, k = i & 255;
        w[a][k] = (a < 2) ? g_wn[a * DM + k] : g_we[(a - 2) * DM + k];
    }
    __syncthreads();
    int warp = tid >> 5, lane = tid & 31;
    int n = blockIdx.x * 8 + warp;
    int kb = lane * 8;
    float4 v0 = *(const float4*)&g_h1[(size_t)n * DM + kb];
    float4 v1 = *(const float4*)&g_h1[(size_t)n * DM + kb + 4];
    float acc[4];
#pragma unroll
    for (int a = 0; a < 4; a++) {
        const float* wa = &w[a][kb];
        acc[a] = v0.x * wa[0] + v0.y * wa[1] + v0.z * wa[2] + v0.w * wa[3]
               + v1.x * wa[4] + v1.y * wa[5] + v1.z * wa[6] + v1.w * wa[7];
#pragma unroll
        for (int o = 16; o; o >>= 1) acc[a] += __shfl_xor_sync(0xffffffffu, acc[a], o);
    }
    if (lane == 0) {
        g_sn[n * 2] = acc[0];
        g_sn[n * 2 + 1] = acc[1];
        g_tn[n * 2] = acc[2];
        g_tn[n * 2 + 1] = acc[3];
    }
}

// ------------------------- se[e,h] = sum_i tn[n_i,h] -------------------------
__global__ void k_se(const int* __restrict__ idx_n) {
    int gw = (blockIdx.x * blockDim.x + threadIdx.x) >> 5;
    int lane = threadIdx.x & 31;
    if (gw >= NE) return;
    int s = g_off_e[gw], t = g_off_e[gw + 1];
    float a0 = 0.f, a1 = 0.f;
    for (int j = s + lane; j < t; j += 32) {
        int n = idx_n[g_perm_e[j]];
        a0 += g_tn[n * 2];
        a1 += g_tn[n * 2 + 1];
    }
#pragma unroll
    for (int o = 16; o; o >>= 1) {
        a0 += __shfl_xor_sync(0xffffffffu, a0, o);
        a1 += __shfl_xor_sync(0xffffffffu, a1, o);
    }
    if (lane == 0) {
        g_se[gw * 2] = a0;
        g_se[gw * 2 + 1] = a1;
    }
}

// ------------------------- per-node segment softmax -------------------------
__global__ void k_softmax(const int* __restrict__ idx_e) {
    int n = blockIdx.x * blockDim.x + threadIdx.x;
    if (n >= NN) return;
    int s = g_off_n[n], t = g_off_n[n + 1];
    int deg = t - s;
    g_dinv[n] = deg > 0 ? 1.0f / (float)deg : 0.0f;
    if (deg == 0) return;
    float sn0 = g_sn[n * 2], sn1 = g_sn[n * 2 + 1];
    float m0 = -3.402823e38f, m1 = -3.402823e38f;
    for (int j = s; j < t; j++) {
        int i = g_perm_n[j];
        int e = idx_e[i];
        float a0 = leaky(sn0 + g_se[e * 2]);
        float a1 = leaky(sn1 + g_se[e * 2 + 1]);
        m0 = fmaxf(m0, a0);
        m1 = fmaxf(m1, a1);
    }
    float d0 = 0.f, d1 = 0.f;
    for (int j = s; j < t; j++) {
        int i = g_perm_n[j];
        int e = idx_e[i];
        float e0 = expf(leaky(sn0 + g_se[e * 2]) - m0);
        float e1 = expf(leaky(sn1 + g_se[e * 2 + 1]) - m1);
        d0 += e0;
        d1 += e1;
        g_alpha[i * 2] = e0;
        g_alpha[i * 2 + 1] = e1;
    }
    float r0 = 1.0f / (d0 + 1e-16f);
    float r1 = 1.0f / (d1 + 1e-16f);
    for (int j = s; j < t; j++) {
        int i = g_perm_n[j];
        g_alpha[i * 2] *= r0;
        g_alpha[i * 2 + 1] *= r1;
    }
}

// ------------------------- alpha-weighted edge aggregation (fp16 out) -------------
__global__ void __launch_bounds__(256) k_agg(const int* __restrict__ idx_n) {
    int e = blockIdx.x;
    int d = threadIdx.x;   // 256
    int s = g_off_e[e], t = g_off_e[e + 1];
    float binv = (t > s) ? 1.0f / (float)(t - s) : 0.0f;
    float a0 = 0.f, a1 = 0.f;
    for (int j = s; j < t; j++) {
        int i = g_perm_e[j];
        int n = idx_n[i];
        float v = g_h1[(size_t)n * DM + d];
        a0 += g_alpha[i * 2] * v;
        a1 += g_alpha[i * 2 + 1] * v;
    }
    g_agg16[(size_t)e * DM + d] = __float2half_rn(binv * a0);
    g_agg16[(size_t)(NE + e) * DM + d] = __float2half_rn(binv * a1);
}

// ------------------------- node_out + mean heads + cb + bn2 (fp16 out) -----------
__global__ void __launch_bounds__(256) k_nodeout(
    const int* __restrict__ idx_e, const float* __restrict__ cb,
    const float* __restrict__ g2, const float* __restrict__ b2,
    const float* __restrict__ m2, const float* __restrict__ v2) {
    int n = blockIdx.x;
    int d = threadIdx.x;   // 256
    int s = g_off_n[n], t = g_off_n[n + 1];
    float acc0 = 0.f, acc1 = 0.f;
    for (int j = s; j < t; j++) {
        int i = g_perm_n[j];
        int e = idx_e[i];
        acc0 += g_alpha[i * 2] * g_eout[(size_t)e * DM + d];
        acc1 += g_alpha[i * 2 + 1] * g_eout[(size_t)(NE + e) * DM + d];
    }
    float x2 = g_dinv[n] * 0.5f * (acc0 + acc1) + cb[d];
    float v = g_h1[(size_t)n * DM + d] + x2;
    v = g2[d] * (v - m2[d]) * rsqrtf(v2[d] + EPSV) + b2[d];
    g_hb16[(size_t)n * DM + d] = __float2half_rn(v);
}

// ------------------------- launch -------------------------
extern "C" void kernel_launch(void* const* d_in, const int* in_sizes, int n_in,
                              void* d_out, int out_size) {
    const float* x    = (const float*)d_in[0];
    const int*   he   = (const int*)d_in[1];
    const int*   idx_n = he;
    const int*   idx_e = he + NI;
    const float* W1   = (const float*)d_in[2];
    const float* b1   = (const float*)d_in[3];
    const float* bn1g = (const float*)d_in[4];
    const float* bn1b = (const float*)d_in[5];
    const float* bn1m = (const float*)d_in[6];
    const float* bn1v = (const float*)d_in[7];
    const float* attW = (const float*)d_in[8];
    const float* att  = (const float*)d_in[9];
    const float* cb   = (const float*)d_in[10];
    const float* bn2g = (const float*)d_in[11];
    const float* bn2b = (const float*)d_in[12];
    const float* bn2m = (const float*)d_in[13];
    const float* bn2v = (const float*)d_in[14];
    const float* W2   = (const float*)d_in[15];
    const float* b2   = (const float*)d_in[16];
    const float* lng  = (const float*)d_in[17];
    const float* lnb  = (const float*)d_in[18];
    float* out = (float*)d_out;

    float *p_h1, *p_eout;
    __half *p_x16, *p_W1h, *p_W2h, *p_attWh, *p_agg16, *p_hb16;
    int *p_cnt_n, *p_cnt_e, *p_off_n, *p_off_e, *p_cur_n, *p_cur_e;
    int *p_bsum_n, *p_bsum_e;
    cudaGetSymbolAddress((void**)&p_h1, g_h1);
    cudaGetSymbolAddress((void**)&p_eout, g_eout);
    cudaGetSymbolAddress((void**)&p_x16, g_x16);
    cudaGetSymbolAddress((void**)&p_W1h, g_W1h);
    cudaGetSymbolAddress((void**)&p_W2h, g_W2h);
    cudaGetSymbolAddress((void**)&p_attWh, g_attWh);
    cudaGetSymbolAddress((void**)&p_agg16, g_agg16);
    cudaGetSymbolAddress((void**)&p_hb16, g_hb16);
    cudaGetSymbolAddress((void**)&p_cnt_n, g_cnt_n);
    cudaGetSymbolAddress((void**)&p_cnt_e, g_cnt_e);
    cudaGetSymbolAddress((void**)&p_off_n, g_off_n);
    cudaGetSymbolAddress((void**)&p_off_e, g_off_e);
    cudaGetSymbolAddress((void**)&p_cur_n, g_cur_n);
    cudaGetSymbolAddress((void**)&p_cur_e, g_cur_e);
    cudaGetSymbolAddress((void**)&p_bsum_n, g_bsum_n);
    cudaGetSymbolAddress((void**)&p_bsum_e, g_bsum_e);

    // ---- fp16 conversions ----
    k_cvt<<<(NN * DM / 4 + 255) / 256, 256>>>(x, p_x16, NN * DM);
    k_cvt<<<(DM * DM / 4 + 255) / 256, 256>>>(W1, p_W1h, DM * DM);
    k_cvt<<<(DM * DM / 4 + 255) / 256, 256>>>(W2, p_W2h, DM * DM);
    k_cvt<<<(2 * DM * DM / 4 + 255) / 256, 256>>>(attW, p_attWh, 2 * DM * DM);

    // ---- CSR build ----
    k_zero_int<<<(NN + 255) / 256, 256>>>(p_cnt_n, NN);
    k_zero_int<<<(NE + 255) / 256, 256>>>(p_cnt_e, NE);
    k_hist<<<(NI + 255) / 256, 256>>>(idx_n, idx_e);
    k_scan_local<<<NN / 1024, 1024>>>(p_cnt_n, p_off_n, p_bsum_n, NN);
    k_scan_local<<<NE / 1024, 1024>>>(p_cnt_e, p_off_e, p_bsum_e, NE);
    k_scan_final<<<NN / 1024, 1024>>>(p_off_n, p_cur_n, p_bsum_n, NN / 1024, NN);
    k_scan_final<<<NE / 1024, 1024>>>(p_off_e, p_cur_e, p_bsum_e, NE / 1024, NE);
    k_scatter<<<(NI + 255) / 256, 256>>>(idx_n, idx_e);

    // ---- contracted attention weight vectors ----
    k_prepw<<<1, 512>>>(attW, att);

    // ---- GEMM 1: h1 = bn1(leaky(x @ W1^T + b1)) ----
    {
        dim3 grid(DM / 128, NN / 128, 1);
        k_gemm_mma<0><<<grid, 256>>>(p_x16, p_W1h, p_h1, DM, b1, bn1g, bn1b, bn1m, bn1v,
                                     0, 0, 0);
    }

    // ---- node dots (sn, tn) + edge scores via scalar segment sum ----
    k_dot2<<<NN / 8, 256>>>();
    k_se<<<NE * 32 / 256, 256>>>(idx_n);

    // ---- segment softmax ----
    k_softmax<<<(NN + 255) / 256, 256>>>(idx_e);

    // ---- alpha-weighted aggregation (fp16 out) ----
    k_agg<<<NE, 256>>>(idx_n);

    // ---- edge GEMM: eout[h] = agg[h] @ attW_h^T  (2 x [4096,256,256]) ----
    {
        dim3 grid(DM / 128, NE / 128, 2);
        k_gemm_mma<1><<<grid, 256>>>(p_agg16, p_attWh, p_eout, DM,
                                     nullptr, nullptr, nullptr, nullptr, nullptr,
                                     (size_t)NE * DM, (size_t)DM * DM, (size_t)NE * DM);
    }

    // ---- node aggregation + bn2 (fp16 out) ----
    k_nodeout<<<NN, 256>>>(idx_e, cb, bn2g, bn2b, bn2m, bn2v);

    // ---- GEMM 3 fused residual + LayerNorm: out = LN(x + leaky(hb @ W2^T + b2)) ----
    {
        dim3 grid(DM / 128, NN / 128, 1);
        k_gemm_mma<3><<<grid, 256>>>(p_hb16, p_W2h, out, DM, b2, lng, lnb, x, nullptr,
                                     0, 0, 0);
    }
}